// round 9
// baseline (speedup 1.0000x reference)
#include <cuda_runtime.h>
#include <cstdint>

#define T_TOK 8192
#define DIM   1024
#define HID   4096
#define NEXP  8
#define BM 128
#define BN 128
#define BK 32
#define NMPAD  136
#define MAXPAD (NMPAD * BM)

#define SA 36                       // smem row stride (floats), A and B tiles
#define ASTG (BM * SA)              // 4608 floats
#define BSTG (BN * SA)              // 4608 floats
#define STGF (ASTG + BSTG)          // 9216 floats per stage
#define STGB (STGF * 4)             // 36864 bytes
#define SMEM_DYN (3 * STGB)         // 110592 bytes -> 2 CTAs/SM

// ---------------- scratch ----------------
__device__ float g_hg[(size_t)MAXPAD * HID];   // h = silu(g)*u (pre-rounded)
__device__ float g_hu[(size_t)MAXPAD * HID];   // raw gate accumulators g
__device__ float g_xc[(size_t)T_TOK * DIM];    // x pre-rounded to tf32
__device__ float g_wgT[(size_t)NEXP * HID * DIM]; // w_gate^T [e][n][k], rounded
__device__ float g_wuT[(size_t)NEXP * HID * DIM]; // w_up^T
__device__ float g_wdT[(size_t)NEXP * DIM * HID]; // w_down^T [e][n][k]
__device__ int   g_perm[MAXPAD];
__device__ float g_permw[MAXPAD];
__device__ int   g_offpad[NEXP + 1];
__device__ int   g_cnt[NEXP];
__device__ int   g_cursor[NEXP];
__device__ float g_probsum[NEXP];
__device__ int   g_topi[T_TOK * 2];
__device__ float g_topw[T_TOK * 2];

// ---------------- helpers ----------------
__device__ __forceinline__ uint32_t smem_u32(const void* p) {
    uint32_t a;
    asm("{ .reg .u64 t; cvta.to.shared.u64 t, %1; cvt.u32.u64 %0, t; }"
        : "=r"(a) : "l"(p));
    return a;
}
__device__ __forceinline__ float frna(float x) {
    uint32_t o; asm("cvt.rna.tf32.f32 %0, %1;" : "=r"(o) : "f"(x));
    return __uint_as_float(o);
}
__device__ __forceinline__ void cp16(uint32_t d, const float* s, uint32_t sz) {
    asm volatile("cp.async.cg.shared.global [%0], [%1], 16, %2;"
                 :: "r"(d), "l"(s), "r"(sz));
}
#define CP_COMMIT() asm volatile("cp.async.commit_group;" ::: "memory")
#define CP_WAIT1()  asm volatile("cp.async.wait_group 1;" ::: "memory")

__device__ __forceinline__ void mma_tf32(float* c, const uint32_t* a,
                                         const uint32_t* b) {
    asm volatile(
        "mma.sync.aligned.m16n8k8.row.col.f32.tf32.tf32.f32 "
        "{%0,%1,%2,%3}, {%4,%5,%6,%7}, {%8,%9}, {%0,%1,%2,%3};"
        : "+f"(c[0]), "+f"(c[1]), "+f"(c[2]), "+f"(c[3])
        : "r"(a[0]), "r"(a[1]), "r"(a[2]), "r"(a[3]), "r"(b[0]), "r"(b[1]));
}

__device__ __forceinline__ void ldsm_x4(uint32_t* r, uint32_t addr) {
    asm volatile("ldmatrix.sync.aligned.m8n8.x4.shared.b16 {%0,%1,%2,%3}, [%4];"
                 : "=r"(r[0]), "=r"(r[1]), "=r"(r[2]), "=r"(r[3]) : "r"(addr));
}

// ---------------- small kernels ----------------
__global__ void k_init() {
    int i = blockIdx.x * blockDim.x + threadIdx.x;
    if (i < NEXP) { g_cnt[i] = 0; g_cursor[i] = 0; g_probsum[i] = 0.f; }
    if (i < MAXPAD) g_perm[i] = -1;
}

__global__ void k_zero_out(float4* out, int n4) {
    float4 z = make_float4(0.f, 0.f, 0.f, 0.f);
    for (int i = blockIdx.x * blockDim.x + threadIdx.x; i < n4;
         i += gridDim.x * blockDim.x)
        out[i] = z;
}

// pre-round x -> g_xc (dst global resolved in device code)
__global__ void k_roundx(const float4* __restrict__ src, int n4) {
    float4* dst = (float4*)g_xc;
    for (int i = blockIdx.x * blockDim.x + threadIdx.x; i < n4;
         i += gridDim.x * blockDim.x) {
        float4 v = src[i];
        v.x = frna(v.x); v.y = frna(v.y); v.z = frna(v.z); v.w = frna(v.w);
        dst[i] = v;
    }
}

// transpose+round: src [e][R][C] -> dst [e][C][R] with frna
__global__ void k_tr(const float* __restrict__ src, int R, int C, int sel) {
    float* dstb = (sel == 0) ? g_wgT : (sel == 1) ? g_wuT : g_wdT;
    __shared__ float t[32][33];
    size_t mo = (size_t)blockIdx.z * R * C;
    const float* s = src + mo;
    float* d = dstb + mo;
    int c0 = blockIdx.x * 32, r0 = blockIdx.y * 32;
#pragma unroll
    for (int j = threadIdx.y; j < 32; j += 8)
        t[j][threadIdx.x] = s[(size_t)(r0 + j) * C + c0 + threadIdx.x];
    __syncthreads();
#pragma unroll
    for (int j = threadIdx.y; j < 32; j += 8)
        d[(size_t)(c0 + j) * R + r0 + threadIdx.x] = frna(t[threadIdx.x][j]);
}

__global__ void k_gate(const float* __restrict__ x, const float* __restrict__ gw) {
    int gwarp = (blockIdx.x * blockDim.x + threadIdx.x) >> 5;
    int lane  = threadIdx.x & 31;
    if (gwarp >= T_TOK) return;
    const float* xr = x + (size_t)gwarp * DIM;

    float acc[NEXP];
#pragma unroll
    for (int e = 0; e < NEXP; e++) acc[e] = 0.f;
    for (int i = lane; i < DIM; i += 32) {
        float xv = xr[i];
        float4 g0 = *(const float4*)(gw + (size_t)i * NEXP);
        float4 g1 = *(const float4*)(gw + (size_t)i * NEXP + 4);
        acc[0] += xv * g0.x; acc[1] += xv * g0.y;
        acc[2] += xv * g0.z; acc[3] += xv * g0.w;
        acc[4] += xv * g1.x; acc[5] += xv * g1.y;
        acc[6] += xv * g1.z; acc[7] += xv * g1.w;
    }
#pragma unroll
    for (int off = 16; off > 0; off >>= 1)
#pragma unroll
        for (int e = 0; e < NEXP; e++)
            acc[e] += __shfl_xor_sync(0xffffffffu, acc[e], off);

    float mx = acc[0];
#pragma unroll
    for (int e = 1; e < NEXP; e++) mx = fmaxf(mx, acc[e]);
    float p[NEXP], s = 0.f;
#pragma unroll
    for (int e = 0; e < NEXP; e++) { p[e] = __expf(acc[e] - mx); s += p[e]; }
    float inv = 1.f / s;
    if (lane < NEXP) atomicAdd(&g_probsum[lane], p[lane] * inv);

    if (lane == 0) {
        int i0 = 0;
#pragma unroll
        for (int e = 1; e < NEXP; e++) if (acc[e] > acc[i0]) i0 = e;
        int i1 = (i0 == 0) ? 1 : 0;
#pragma unroll
        for (int e = 0; e < NEXP; e++)
            if (e != i0 && acc[e] > acc[i1]) i1 = e;
        float m2 = fmaxf(acc[i0], acc[i1]);
        float e0 = __expf(acc[i0] - m2), e1 = __expf(acc[i1] - m2);
        float inv2 = 1.f / (e0 + e1);
        g_topi[2 * gwarp]     = i0; g_topw[2 * gwarp]     = e0 * inv2;
        g_topi[2 * gwarp + 1] = i1; g_topw[2 * gwarp + 1] = e1 * inv2;
        atomicAdd(&g_cnt[i0], 1);
        atomicAdd(&g_cnt[i1], 1);
    }
}

__global__ void k_offsets(float* __restrict__ out) {
    if (threadIdx.x != 0 || blockIdx.x != 0) return;
    int off = 0;
    for (int e = 0; e < NEXP; e++) {
        g_offpad[e] = off;
        off += ((g_cnt[e] + BM - 1) / BM) * BM;
    }
    g_offpad[NEXP] = off;
    float loss = 0.f;
    const float invT = 1.f / (float)T_TOK;
    for (int e = 0; e < NEXP; e++) {
        float m = g_probsum[e] * invT;
        out[(size_t)T_TOK * DIM + 1 + e] = m;
        loss += m * m;
    }
    out[(size_t)T_TOK * DIM] = (float)NEXP * loss;
}

__global__ void k_scatter() {
    int t = blockIdx.x * blockDim.x + threadIdx.x;
    if (t >= 2 * T_TOK) return;
    int e = g_topi[t];
    int pos = g_offpad[e] + atomicAdd(&g_cursor[e], 1);
    g_perm[pos]  = t >> 1;
    g_permw[pos] = g_topw[t];
}

// ---------------- shared GEMM mainloop pieces ----------------
// A tile [128 rows][32 k] and B tile [128 n-rows][32 k], both stride SA, both
// pre-rounded tf32 in gmem -> no in-loop rounding, all fragments via ldmatrix.

// ---------------- GEMM1 core (gate or up), A = g_xc gathered ----------------
template<int UP>
__device__ __forceinline__ void gemm1_body(const float* __restrict__ wT) {
    extern __shared__ float sm[];
    int total = g_offpad[NEXP];
    int mbase = blockIdx.y * BM;
    if (mbase >= total) return;
    int e = 0;
#pragma unroll
    for (int i = 0; i < NEXP; i++) if (mbase >= g_offpad[i + 1]) e = i + 1;

    const float* W = wT + (size_t)e * DIM * HID;   // [n=HID][k=DIM]
    int ncol = blockIdx.x * BN;

    int tid = threadIdx.x;
    uint32_t smb = smem_u32(sm);

    int row0 = tid >> 3, akf = (tid & 7) * 4;
    uint32_t adst[4], bdst[4];
    const float *asrc[4], *bsrc[4];
    uint32_t asz[4];
#pragma unroll
    for (int p = 0; p < 4; p++) {
        int row = row0 + p * 32;
        adst[p] = (uint32_t)(row * SA + akf) * 4;
        bdst[p] = (uint32_t)(ASTG + row * SA + akf) * 4;
        int tok = g_perm[mbase + row];
        asrc[p] = g_xc + ((tok >= 0) ? (size_t)tok * DIM : 0) + akf;
        asz[p]  = (tok >= 0) ? 16u : 0u;
        bsrc[p] = W + (size_t)(ncol + row) * DIM + akf;
    }

    int lane = tid & 31, gid = lane >> 2, tig = lane & 3;
    int wm = (tid >> 5) & 3, wn = tid >> 7;
    uint32_t aln = (uint32_t)(((wm * 32 + (lane & 15)) * SA + (lane >> 4) * 4) * 4);
    uint32_t bln = (uint32_t)((ASTG +
        (wn * 64 + (lane & 7) + ((lane >> 4) << 3)) * SA +
        ((lane >> 3) & 1) * 4) * 4);

    float acc[2][8][4];
#pragma unroll
    for (int mt = 0; mt < 2; mt++)
#pragma unroll
        for (int nt = 0; nt < 8; nt++)
#pragma unroll
            for (int q = 0; q < 4; q++) acc[mt][nt][q] = 0.f;

    const int NT = DIM / BK;             // 32
#pragma unroll
    for (int t = 0; t < 2; t++) {
        uint32_t base = smb + t * STGB;
        int k0 = t * BK;
#pragma unroll
        for (int p = 0; p < 4; p++) cp16(base + adst[p], asrc[p] + k0, asz[p]);
#pragma unroll
        for (int p = 0; p < 4; p++) cp16(base + bdst[p], bsrc[p] + k0, 16);
        CP_COMMIT();
    }

    for (int i = 0; i < NT; i++) {
        CP_WAIT1();
        __syncthreads();
        int t = i + 2;
        if (t < NT) {
            uint32_t base = smb + (t % 3) * STGB;
            int k0 = t * BK;
#pragma unroll
            for (int p = 0; p < 4; p++) cp16(base + adst[p], asrc[p] + k0, asz[p]);
#pragma unroll
            for (int p = 0; p < 4; p++) cp16(base + bdst[p], bsrc[p] + k0, 16);
        }
        CP_COMMIT();

        uint32_t stg = smb + (uint32_t)(i % 3) * STGB;
#pragma unroll
        for (int ks = 0; ks < 4; ks++) {
            uint32_t a[2][4], b[4][4];
#pragma unroll
            for (int mt = 0; mt < 2; mt++)
                ldsm_x4(a[mt], stg + aln + (uint32_t)(mt * 16 * SA * 4 + ks * 32));
#pragma unroll
            for (int j = 0; j < 4; j++)
                ldsm_x4(b[j], stg + bln + (uint32_t)(j * 16 * SA * 4 + ks * 32));
#pragma unroll
            for (int mt = 0; mt < 2; mt++)
#pragma unroll
                for (int j = 0; j < 4; j++) {
                    mma_tf32(acc[mt][2 * j],     a[mt], &b[j][0]);
                    mma_tf32(acc[mt][2 * j + 1], a[mt], &b[j][2]);
                }
        }
    }

#pragma unroll
    for (int mt = 0; mt < 2; mt++) {
        int r = mbase + wm * 32 + mt * 16 + gid;
#pragma unroll
        for (int nt = 0; nt < 8; nt++) {
            int c = ncol + wn * 64 + nt * 8 + 2 * tig;
            if (UP) {
                float2 ga = *(float2*)&g_hu[(size_t)r * HID + c];
                float2 gb = *(float2*)&g_hu[(size_t)(r + 8) * HID + c];
                float h0 = frna(ga.x * (1.f / (1.f + __expf(-ga.x))) * acc[mt][nt][0]);
                float h1 = frna(ga.y * (1.f / (1.f + __expf(-ga.y))) * acc[mt][nt][1]);
                float h2 = frna(gb.x * (1.f / (1.f + __expf(-gb.x))) * acc[mt][nt][2]);
                float h3 = frna(gb.y * (1.f / (1.f + __expf(-gb.y))) * acc[mt][nt][3]);
                *(float2*)&g_hg[(size_t)r * HID + c]       = make_float2(h0, h1);
                *(float2*)&g_hg[(size_t)(r + 8) * HID + c] = make_float2(h2, h3);
            } else {
                *(float2*)&g_hu[(size_t)r * HID + c] =
                    make_float2(acc[mt][nt][0], acc[mt][nt][1]);
                *(float2*)&g_hu[(size_t)(r + 8) * HID + c] =
                    make_float2(acc[mt][nt][2], acc[mt][nt][3]);
            }
        }
    }
}

__global__ __launch_bounds__(256) void k_g1gate() { gemm1_body<0>(g_wgT); }
__global__ __launch_bounds__(256) void k_g1up()   { gemm1_body<1>(g_wuT); }

// ---------------- GEMM2: A = g_hg, B = g_wdT, atomic epilogue ----------------
__global__ __launch_bounds__(256) void k_gemm2_mma(float* __restrict__ out) {
    extern __shared__ float sm[];
    int total = g_offpad[NEXP];
    int mbase = blockIdx.y * BM;
    if (mbase >= total) return;
    int e = 0;
#pragma unroll
    for (int i = 0; i < NEXP; i++) if (mbase >= g_offpad[i + 1]) e = i + 1;

    const float* W = g_wdT + (size_t)e * DIM * HID;   // [n=DIM][k=HID]
    int ncol = blockIdx.x * BN;

    int tid = threadIdx.x;
    uint32_t smb = smem_u32(sm);

    int row0 = tid >> 3, akf = (tid & 7) * 4;
    uint32_t adst[4], bdst[4];
    const float *asrc[4], *bsrc[4];
#pragma unroll
    for (int p = 0; p < 4; p++) {
        int row = row0 + p * 32;
        adst[p] = (uint32_t)(row * SA + akf) * 4;
        bdst[p] = (uint32_t)(ASTG + row * SA + akf) * 4;
        asrc[p] = g_hg + (size_t)(mbase + row) * HID + akf;
        bsrc[p] = W + (size_t)(ncol + row) * HID + akf;
    }

    int lane = tid & 31, gid = lane >> 2, tig = lane & 3;
    int wm = (tid >> 5) & 3, wn = tid >> 7;
    uint32_t aln = (uint32_t)(((wm * 32 + (lane & 15)) * SA + (lane >> 4) * 4) * 4);
    uint32_t bln = (uint32_t)((ASTG +
        (wn * 64 + (lane & 7) + ((lane >> 4) << 3)) * SA +
        ((lane >> 3) & 1) * 4) * 4);

    float acc[2][8][4];
#pragma unroll
    for (int mt = 0; mt < 2; mt++)
#pragma unroll
        for (int nt = 0; nt < 8; nt++)
#pragma unroll
            for (int q = 0; q < 4; q++) acc[mt][nt][q] = 0.f;

    const int NT = HID / BK;            // 128
#pragma unroll
    for (int t = 0; t < 2; t++) {
        uint32_t base = smb + t * STGB;
        int k0 = t * BK;
#pragma unroll
        for (int p = 0; p < 4; p++) cp16(base + adst[p], asrc[p] + k0, 16);
#pragma unroll
        for (int p = 0; p < 4; p++) cp16(base + bdst[p], bsrc[p] + k0, 16);
        CP_COMMIT();
    }

    for (int i = 0; i < NT; i++) {
        CP_WAIT1();
        __syncthreads();
        int t = i + 2;
        if (t < NT) {
            uint32_t base = smb + (t % 3) * STGB;
            int k0 = t * BK;
#pragma unroll
            for (int p = 0; p < 4; p++) cp16(base + adst[p], asrc[p] + k0, 16);
#pragma unroll
            for (int p = 0; p < 4; p++) cp16(base + bdst[p], bsrc[p] + k0, 16);
        }
        CP_COMMIT();

        uint32_t stg = smb + (uint32_t)(i % 3) * STGB;
#pragma unroll
        for (int ks = 0; ks < 4; ks++) {
            uint32_t a[2][4], b[4][4];
#pragma unroll
            for (int mt = 0; mt < 2; mt++)
                ldsm_x4(a[mt], stg + aln + (uint32_t)(mt * 16 * SA * 4 + ks * 32));
#pragma unroll
            for (int j = 0; j < 4; j++)
                ldsm_x4(b[j], stg + bln + (uint32_t)(j * 16 * SA * 4 + ks * 32));
#pragma unroll
            for (int mt = 0; mt < 2; mt++)
#pragma unroll
                for (int j = 0; j < 4; j++) {
                    mma_tf32(acc[mt][2 * j],     a[mt], &b[j][0]);
                    mma_tf32(acc[mt][2 * j + 1], a[mt], &b[j][2]);
                }
        }
    }

#pragma unroll
    for (int mt = 0; mt < 2; mt++) {
        int slot = mbase + wm * 32 + mt * 16 + gid;
        int tok0 = g_perm[slot],     tok1 = g_perm[slot + 8];
        float w0 = g_permw[slot],    w1 = g_permw[slot + 8];
#pragma unroll
        for (int nt = 0; nt < 8; nt++) {
            int c = ncol + wn * 64 + nt * 8 + 2 * tig;
            if (tok0 >= 0) {
                float* op = out + (size_t)tok0 * DIM + c;
                atomicAdd(op,     w0 * acc[mt][nt][0]);
                atomicAdd(op + 1, w0 * acc[mt][nt][1]);
            }
            if (tok1 >= 0) {
                float* op = out + (size_t)tok1 * DIM + c;
                atomicAdd(op,     w1 * acc[mt][nt][2]);
                atomicAdd(op + 1, w1 * acc[mt][nt][3]);
            }
        }
    }
}

// ---------------- launch ----------------
extern "C" void kernel_launch(void* const* d_in, const int* in_sizes, int n_in,
                              void* d_out, int out_size) {
    const float* x      = (const float*)d_in[0];
    const float* gate_w = (const float*)d_in[1];
    const float* w_gate = (const float*)d_in[2];
    const float* w_up   = (const float*)d_in[3];
    const float* w_down = (const float*)d_in[4];
    float* out = (float*)d_out;

    cudaFuncSetAttribute(k_g1gate, cudaFuncAttributeMaxDynamicSharedMemorySize,
                         SMEM_DYN);
    cudaFuncSetAttribute(k_g1up, cudaFuncAttributeMaxDynamicSharedMemorySize,
                         SMEM_DYN);
    cudaFuncSetAttribute(k_gemm2_mma, cudaFuncAttributeMaxDynamicSharedMemorySize,
                         SMEM_DYN);

    k_init<<<MAXPAD / 256, 256>>>();
    k_zero_out<<<2048, 256>>>((float4*)out, (T_TOK * DIM) / 4);
    k_gate<<<T_TOK / 8, 256>>>(x, gate_w);
    k_offsets<<<1, 32>>>(out);
    k_scatter<<<(2 * T_TOK) / 256, 256>>>();

    k_roundx<<<2048, 256>>>((const float4*)x, (T_TOK * DIM) / 4);
    dim3 trb(32, 8);
    k_tr<<<dim3(HID / 32, DIM / 32, NEXP), trb>>>(w_gate, DIM, HID, 0);
    k_tr<<<dim3(HID / 32, DIM / 32, NEXP), trb>>>(w_up,   DIM, HID, 1);
    k_tr<<<dim3(DIM / 32, HID / 32, NEXP), trb>>>(w_down, HID, DIM, 2);

    k_g1gate<<<dim3(HID / BN, NMPAD), 256, SMEM_DYN>>>();
    k_g1up<<<dim3(HID / BN, NMPAD), 256, SMEM_DYN>>>();
    k_gemm2_mma<<<dim3(DIM / BN, NMPAD), 256, SMEM_DYN>>>(out);
}

// round 10
// speedup vs baseline: 1.4749x; 1.4749x over previous
#include <cuda_runtime.h>
#include <cuda_fp16.h>
#include <cstdint>

#define T_TOK 8192
#define DIM   1024
#define HID   4096
#define NEXP  8
#define BM 128
#define BN 128
#define BK 32                      // k elements per stage
#define NMPAD  136
#define MAXPAD (NMPAD * BM)

#define SAH 40                     // smem row stride in halves (80 bytes)
#define ATILEH (BM * SAH)          // 5120 halves per tile
#define STGH (2 * ATILEH)          // 10240 halves per stage (A+B)
#define STGB (STGH * 2)            // 20480 bytes
#define SMEM_DYN (3 * STGB)        // 61440 bytes

// ---------------- scratch ----------------
__device__ float  g_hu[(size_t)MAXPAD * HID];      // raw gate accumulators g (fp32)
__device__ __half g_hh[(size_t)MAXPAD * HID];      // h = silu(g)*u in fp16
__device__ __half g_xh[(size_t)T_TOK * DIM];       // x in fp16
__device__ __half g_wgT[(size_t)NEXP * HID * DIM]; // w_gate^T [e][n][k] fp16
__device__ __half g_wuT[(size_t)NEXP * HID * DIM];
__device__ __half g_wdT[(size_t)NEXP * DIM * HID];
__device__ int    g_perm[MAXPAD];
__device__ float  g_permw[MAXPAD];
__device__ int    g_offpad[NEXP + 1];
__device__ int    g_cnt[NEXP];
__device__ int    g_cursor[NEXP];
__device__ float  g_probsum[NEXP];
__device__ int    g_topi[T_TOK * 2];
__device__ float  g_topw[T_TOK * 2];

// ---------------- helpers ----------------
__device__ __forceinline__ uint32_t smem_u32(const void* p) {
    uint32_t a;
    asm("{ .reg .u64 t; cvta.to.shared.u64 t, %1; cvt.u32.u64 %0, t; }"
        : "=r"(a) : "l"(p));
    return a;
}
__device__ __forceinline__ void cp16h(uint32_t d, const __half* s, uint32_t sz) {
    asm volatile("cp.async.cg.shared.global [%0], [%1], 16, %2;"
                 :: "r"(d), "l"(s), "r"(sz));
}
#define CP_COMMIT() asm volatile("cp.async.commit_group;" ::: "memory")
#define CP_WAIT1()  asm volatile("cp.async.wait_group 1;" ::: "memory")

__device__ __forceinline__ void mma_f16(float* c, const uint32_t* a,
                                        const uint32_t* b) {
    asm volatile(
        "mma.sync.aligned.m16n8k16.row.col.f32.f16.f16.f32 "
        "{%0,%1,%2,%3}, {%4,%5,%6,%7}, {%8,%9}, {%0,%1,%2,%3};"
        : "+f"(c[0]), "+f"(c[1]), "+f"(c[2]), "+f"(c[3])
        : "r"(a[0]), "r"(a[1]), "r"(a[2]), "r"(a[3]), "r"(b[0]), "r"(b[1]));
}

__device__ __forceinline__ void ldsm_x4(uint32_t* r, uint32_t addr) {
    asm volatile("ldmatrix.sync.aligned.m8n8.x4.shared.b16 {%0,%1,%2,%3}, [%4];"
                 : "=r"(r[0]), "=r"(r[1]), "=r"(r[2]), "=r"(r[3]) : "r"(addr));
}

// ---------------- small kernels ----------------
__global__ void k_init() {
    int i = blockIdx.x * blockDim.x + threadIdx.x;
    if (i < NEXP) { g_cnt[i] = 0; g_cursor[i] = 0; g_probsum[i] = 0.f; }
    if (i < MAXPAD) g_perm[i] = -1;
}

__global__ void k_zero_out(float4* out, int n4) {
    float4 z = make_float4(0.f, 0.f, 0.f, 0.f);
    for (int i = blockIdx.x * blockDim.x + threadIdx.x; i < n4;
         i += gridDim.x * blockDim.x)
        out[i] = z;
}

// x fp32 -> fp16
__global__ void k_cvtx(const float4* __restrict__ src, int n4) {
    __half2* dst = (__half2*)g_xh;
    for (int i = blockIdx.x * blockDim.x + threadIdx.x; i < n4;
         i += gridDim.x * blockDim.x) {
        float4 v = src[i];
        dst[2 * i]     = __floats2half2_rn(v.x, v.y);
        dst[2 * i + 1] = __floats2half2_rn(v.z, v.w);
    }
}

// transpose+convert: src fp32 [e][R][C] -> dst fp16 [e][C][R]
__global__ void k_tr(const float* __restrict__ src, int R, int C, int sel) {
    __half* dstb = (sel == 0) ? g_wgT : (sel == 1) ? g_wuT : g_wdT;
    __shared__ float t[32][33];
    size_t mo = (size_t)blockIdx.z * R * C;
    const float* s = src + mo;
    __half* d = dstb + mo;
    int c0 = blockIdx.x * 32, r0 = blockIdx.y * 32;
#pragma unroll
    for (int j = threadIdx.y; j < 32; j += 8)
        t[j][threadIdx.x] = s[(size_t)(r0 + j) * C + c0 + threadIdx.x];
    __syncthreads();
#pragma unroll
    for (int j = threadIdx.y; j < 32; j += 8)
        d[(size_t)(c0 + j) * R + r0 + threadIdx.x] = __float2half_rn(t[threadIdx.x][j]);
}

__global__ void k_gate(const float* __restrict__ x, const float* __restrict__ gw) {
    int gwarp = (blockIdx.x * blockDim.x + threadIdx.x) >> 5;
    int lane  = threadIdx.x & 31;
    if (gwarp >= T_TOK) return;
    const float* xr = x + (size_t)gwarp * DIM;

    float acc[NEXP];
#pragma unroll
    for (int e = 0; e < NEXP; e++) acc[e] = 0.f;
    for (int i = lane; i < DIM; i += 32) {
        float xv = xr[i];
        float4 g0 = *(const float4*)(gw + (size_t)i * NEXP);
        float4 g1 = *(const float4*)(gw + (size_t)i * NEXP + 4);
        acc[0] += xv * g0.x; acc[1] += xv * g0.y;
        acc[2] += xv * g0.z; acc[3] += xv * g0.w;
        acc[4] += xv * g1.x; acc[5] += xv * g1.y;
        acc[6] += xv * g1.z; acc[7] += xv * g1.w;
    }
#pragma unroll
    for (int off = 16; off > 0; off >>= 1)
#pragma unroll
        for (int e = 0; e < NEXP; e++)
            acc[e] += __shfl_xor_sync(0xffffffffu, acc[e], off);

    float mx = acc[0];
#pragma unroll
    for (int e = 1; e < NEXP; e++) mx = fmaxf(mx, acc[e]);
    float p[NEXP], s = 0.f;
#pragma unroll
    for (int e = 0; e < NEXP; e++) { p[e] = __expf(acc[e] - mx); s += p[e]; }
    float inv = 1.f / s;
    if (lane < NEXP) atomicAdd(&g_probsum[lane], p[lane] * inv);

    if (lane == 0) {
        int i0 = 0;
#pragma unroll
        for (int e = 1; e < NEXP; e++) if (acc[e] > acc[i0]) i0 = e;
        int i1 = (i0 == 0) ? 1 : 0;
#pragma unroll
        for (int e = 0; e < NEXP; e++)
            if (e != i0 && acc[e] > acc[i1]) i1 = e;
        float m2 = fmaxf(acc[i0], acc[i1]);
        float e0 = __expf(acc[i0] - m2), e1 = __expf(acc[i1] - m2);
        float inv2 = 1.f / (e0 + e1);
        g_topi[2 * gwarp]     = i0; g_topw[2 * gwarp]     = e0 * inv2;
        g_topi[2 * gwarp + 1] = i1; g_topw[2 * gwarp + 1] = e1 * inv2;
        atomicAdd(&g_cnt[i0], 1);
        atomicAdd(&g_cnt[i1], 1);
    }
}

__global__ void k_offsets(float* __restrict__ out) {
    if (threadIdx.x != 0 || blockIdx.x != 0) return;
    int off = 0;
    for (int e = 0; e < NEXP; e++) {
        g_offpad[e] = off;
        off += ((g_cnt[e] + BM - 1) / BM) * BM;
    }
    g_offpad[NEXP] = off;
    float loss = 0.f;
    const float invT = 1.f / (float)T_TOK;
    for (int e = 0; e < NEXP; e++) {
        float m = g_probsum[e] * invT;
        out[(size_t)T_TOK * DIM + 1 + e] = m;
        loss += m * m;
    }
    out[(size_t)T_TOK * DIM] = (float)NEXP * loss;
}

__global__ void k_scatter() {
    int t = blockIdx.x * blockDim.x + threadIdx.x;
    if (t >= 2 * T_TOK) return;
    int e = g_topi[t];
    int pos = g_offpad[e] + atomicAdd(&g_cursor[e], 1);
    g_perm[pos]  = t >> 1;
    g_permw[pos] = g_topw[t];
}

// ---------------- GEMM1 core (gate or up), fp16 MMA ----------------
// A [128m][32k] fp16, B [128n][32k] fp16, both stride SAH halves.
template<int UP>
__device__ __forceinline__ void gemm1_body(const __half* __restrict__ wT) {
    extern __shared__ __half smh[];
    int total = g_offpad[NEXP];
    int mbase = blockIdx.y * BM;
    if (mbase >= total) return;
    int e = 0;
#pragma unroll
    for (int i = 0; i < NEXP; i++) if (mbase >= g_offpad[i + 1]) e = i + 1;

    const __half* W = wT + (size_t)e * DIM * HID;   // [n=HID][k=DIM]
    int ncol = blockIdx.x * BN;

    int tid = threadIdx.x;
    uint32_t smb = smem_u32(smh);

    // loads: 2 rows/thread (A and B each), 16B chunk = 8 halves
    int chk = (tid & 3) * 8;                 // halves
    uint32_t adst[2], bdst[2];
    const __half *asrc[2], *bsrc[2];
    uint32_t asz[2];
#pragma unroll
    for (int p = 0; p < 2; p++) {
        int row = (tid >> 2) + p * 64;
        adst[p] = (uint32_t)((row * SAH + chk) * 2);
        bdst[p] = (uint32_t)((ATILEH + row * SAH + chk) * 2);
        int tok = g_perm[mbase + row];
        asrc[p] = g_xh + ((tok >= 0) ? (size_t)tok * DIM : 0) + chk;
        asz[p]  = (tok >= 0) ? 16u : 0u;
        bsrc[p] = W + (size_t)(ncol + row) * DIM + chk;
    }

    int lane = tid & 31, gid = lane >> 2, tig = lane & 3;
    int wm = (tid >> 5) & 3, wn = tid >> 7;
    uint32_t aln = (uint32_t)(((wm * 32 + (lane & 15)) * SAH + (lane >> 4) * 8) * 2);
    uint32_t bln = (uint32_t)((ATILEH +
        (wn * 64 + (lane & 7) + ((lane >> 4) << 3)) * SAH +
        ((lane >> 3) & 1) * 8) * 2);

    float acc[2][8][4];
#pragma unroll
    for (int mt = 0; mt < 2; mt++)
#pragma unroll
        for (int nt = 0; nt < 8; nt++)
#pragma unroll
            for (int q = 0; q < 4; q++) acc[mt][nt][q] = 0.f;

    const int NT = DIM / BK;             // 32
#pragma unroll
    for (int t = 0; t < 2; t++) {
        uint32_t base = smb + t * STGB;
        int k0 = t * BK;
#pragma unroll
        for (int p = 0; p < 2; p++) cp16h(base + adst[p], asrc[p] + k0, asz[p]);
#pragma unroll
        for (int p = 0; p < 2; p++) cp16h(base + bdst[p], bsrc[p] + k0, 16);
        CP_COMMIT();
    }

    for (int i = 0; i < NT; i++) {
        CP_WAIT1();
        __syncthreads();
        int t = i + 2;
        if (t < NT) {
            uint32_t base = smb + (t % 3) * STGB;
            int k0 = t * BK;
#pragma unroll
            for (int p = 0; p < 2; p++) cp16h(base + adst[p], asrc[p] + k0, asz[p]);
#pragma unroll
            for (int p = 0; p < 2; p++) cp16h(base + bdst[p], bsrc[p] + k0, 16);
        }
        CP_COMMIT();

        uint32_t stg = smb + (uint32_t)(i % 3) * STGB;
#pragma unroll
        for (int ks = 0; ks < 2; ks++) {      // two k16 steps per BK=32
            uint32_t a[2][4], b[4][4];
#pragma unroll
            for (int mt = 0; mt < 2; mt++)
                ldsm_x4(a[mt], stg + aln + (uint32_t)(mt * 16 * SAH * 2 + ks * 32));
#pragma unroll
            for (int j = 0; j < 4; j++)
                ldsm_x4(b[j], stg + bln + (uint32_t)(j * 16 * SAH * 2 + ks * 32));
#pragma unroll
            for (int mt = 0; mt < 2; mt++)
#pragma unroll
                for (int j = 0; j < 4; j++) {
                    mma_f16(acc[mt][2 * j],     a[mt], &b[j][0]);
                    mma_f16(acc[mt][2 * j + 1], a[mt], &b[j][2]);
                }
        }
    }

#pragma unroll
    for (int mt = 0; mt < 2; mt++) {
        int r = mbase + wm * 32 + mt * 16 + gid;
#pragma unroll
        for (int nt = 0; nt < 8; nt++) {
            int c = ncol + wn * 64 + nt * 8 + 2 * tig;
            if (UP) {
                float2 ga = *(float2*)&g_hu[(size_t)r * HID + c];
                float2 gb = *(float2*)&g_hu[(size_t)(r + 8) * HID + c];
                float h0 = ga.x * (1.f / (1.f + __expf(-ga.x))) * acc[mt][nt][0];
                float h1 = ga.y * (1.f / (1.f + __expf(-ga.y))) * acc[mt][nt][1];
                float h2 = gb.x * (1.f / (1.f + __expf(-gb.x))) * acc[mt][nt][2];
                float h3 = gb.y * (1.f / (1.f + __expf(-gb.y))) * acc[mt][nt][3];
                *(__half2*)&g_hh[(size_t)r * HID + c]       = __floats2half2_rn(h0, h1);
                *(__half2*)&g_hh[(size_t)(r + 8) * HID + c] = __floats2half2_rn(h2, h3);
            } else {
                *(float2*)&g_hu[(size_t)r * HID + c] =
                    make_float2(acc[mt][nt][0], acc[mt][nt][1]);
                *(float2*)&g_hu[(size_t)(r + 8) * HID + c] =
                    make_float2(acc[mt][nt][2], acc[mt][nt][3]);
            }
        }
    }
}

__global__ __launch_bounds__(256) void k_g1gate() { gemm1_body<0>(g_wgT); }
__global__ __launch_bounds__(256) void k_g1up()   { gemm1_body<1>(g_wuT); }

// ---------------- GEMM2: A = g_hh fp16, B = g_wdT fp16, atomic epilogue --------
__global__ __launch_bounds__(256) void k_gemm2_mma(float* __restrict__ out) {
    extern __shared__ __half smh[];
    int total = g_offpad[NEXP];
    int mbase = blockIdx.y * BM;
    if (mbase >= total) return;
    int e = 0;
#pragma unroll
    for (int i = 0; i < NEXP; i++) if (mbase >= g_offpad[i + 1]) e = i + 1;

    const __half* W = g_wdT + (size_t)e * DIM * HID;   // [n=DIM][k=HID]
    int ncol = blockIdx.x * BN;

    int tid = threadIdx.x;
    uint32_t smb = smem_u32(smh);

    int chk = (tid & 3) * 8;
    uint32_t adst[2], bdst[2];
    const __half *asrc[2], *bsrc[2];
#pragma unroll
    for (int p = 0; p < 2; p++) {
        int row = (tid >> 2) + p * 64;
        adst[p] = (uint32_t)((row * SAH + chk) * 2);
        bdst[p] = (uint32_t)((ATILEH + row * SAH + chk) * 2);
        asrc[p] = g_hh + (size_t)(mbase + row) * HID + chk;
        bsrc[p] = W + (size_t)(ncol + row) * HID + chk;
    }

    int lane = tid & 31, gid = lane >> 2, tig = lane & 3;
    int wm = (tid >> 5) & 3, wn = tid >> 7;
    uint32_t aln = (uint32_t)(((wm * 32 + (lane & 15)) * SAH + (lane >> 4) * 8) * 2);
    uint32_t bln = (uint32_t)((ATILEH +
        (wn * 64 + (lane & 7) + ((lane >> 4) << 3)) * SAH +
        ((lane >> 3) & 1) * 8) * 2);

    float acc[2][8][4];
#pragma unroll
    for (int mt = 0; mt < 2; mt++)
#pragma unroll
        for (int nt = 0; nt < 8; nt++)
#pragma unroll
            for (int q = 0; q < 4; q++) acc[mt][nt][q] = 0.f;

    const int NT = HID / BK;            // 128
#pragma unroll
    for (int t = 0; t < 2; t++) {
        uint32_t base = smb + t * STGB;
        int k0 = t * BK;
#pragma unroll
        for (int p = 0; p < 2; p++) cp16h(base + adst[p], asrc[p] + k0, 16);
#pragma unroll
        for (int p = 0; p < 2; p++) cp16h(base + bdst[p], bsrc[p] + k0, 16);
        CP_COMMIT();
    }

    for (int i = 0; i < NT; i++) {
        CP_WAIT1();
        __syncthreads();
        int t = i + 2;
        if (t < NT) {
            uint32_t base = smb + (t % 3) * STGB;
            int k0 = t * BK;
#pragma unroll
            for (int p = 0; p < 2; p++) cp16h(base + adst[p], asrc[p] + k0, 16);
#pragma unroll
            for (int p = 0; p < 2; p++) cp16h(base + bdst[p], bsrc[p] + k0, 16);
        }
        CP_COMMIT();

        uint32_t stg = smb + (uint32_t)(i % 3) * STGB;
#pragma unroll
        for (int ks = 0; ks < 2; ks++) {
            uint32_t a[2][4], b[4][4];
#pragma unroll
            for (int mt = 0; mt < 2; mt++)
                ldsm_x4(a[mt], stg + aln + (uint32_t)(mt * 16 * SAH * 2 + ks * 32));
#pragma unroll
            for (int j = 0; j < 4; j++)
                ldsm_x4(b[j], stg + bln + (uint32_t)(j * 16 * SAH * 2 + ks * 32));
#pragma unroll
            for (int mt = 0; mt < 2; mt++)
#pragma unroll
                for (int j = 0; j < 4; j++) {
                    mma_f16(acc[mt][2 * j],     a[mt], &b[j][0]);
                    mma_f16(acc[mt][2 * j + 1], a[mt], &b[j][2]);
                }
        }
    }

#pragma unroll
    for (int mt = 0; mt < 2; mt++) {
        int slot = mbase + wm * 32 + mt * 16 + gid;
        int tok0 = g_perm[slot],     tok1 = g_perm[slot + 8];
        float w0 = g_permw[slot],    w1 = g_permw[slot + 8];
#pragma unroll
        for (int nt = 0; nt < 8; nt++) {
            int c = ncol + wn * 64 + nt * 8 + 2 * tig;
            if (tok0 >= 0) {
                float* op = out + (size_t)tok0 * DIM + c;
                atomicAdd(op,     w0 * acc[mt][nt][0]);
                atomicAdd(op + 1, w0 * acc[mt][nt][1]);
            }
            if (tok1 >= 0) {
                float* op = out + (size_t)tok1 * DIM + c;
                atomicAdd(op,     w1 * acc[mt][nt][2]);
                atomicAdd(op + 1, w1 * acc[mt][nt][3]);
            }
        }
    }
}

// ---------------- launch ----------------
extern "C" void kernel_launch(void* const* d_in, const int* in_sizes, int n_in,
                              void* d_out, int out_size) {
    const float* x      = (const float*)d_in[0];
    const float* gate_w = (const float*)d_in[1];
    const float* w_gate = (const float*)d_in[2];
    const float* w_up   = (const float*)d_in[3];
    const float* w_down = (const float*)d_in[4];
    float* out = (float*)d_out;

    cudaFuncSetAttribute(k_g1gate, cudaFuncAttributeMaxDynamicSharedMemorySize,
                         SMEM_DYN);
    cudaFuncSetAttribute(k_g1up, cudaFuncAttributeMaxDynamicSharedMemorySize,
                         SMEM_DYN);
    cudaFuncSetAttribute(k_gemm2_mma, cudaFuncAttributeMaxDynamicSharedMemorySize,
                         SMEM_DYN);

    k_init<<<MAXPAD / 256, 256>>>();
    k_zero_out<<<2048, 256>>>((float4*)out, (T_TOK * DIM) / 4);
    k_gate<<<T_TOK / 8, 256>>>(x, gate_w);
    k_offsets<<<1, 32>>>(out);
    k_scatter<<<(2 * T_TOK) / 256, 256>>>();

    k_cvtx<<<2048, 256>>>((const float4*)x, (T_TOK * DIM) / 4);
    dim3 trb(32, 8);
    k_tr<<<dim3(HID / 32, DIM / 32, NEXP), trb>>>(w_gate, DIM, HID, 0);
    k_tr<<<dim3(HID / 32, DIM / 32, NEXP), trb>>>(w_up,   DIM, HID, 1);
    k_tr<<<dim3(DIM / 32, HID / 32, NEXP), trb>>>(w_down, HID, DIM, 2);

    k_g1gate<<<dim3(HID / BN, NMPAD), 256, SMEM_DYN>>>();
    k_g1up<<<dim3(HID / BN, NMPAD), 256, SMEM_DYN>>>();
    k_gemm2_mma<<<dim3(DIM / BN, NMPAD), 256, SMEM_DYN>>>(out);
}

// round 11
// speedup vs baseline: 1.5664x; 1.0621x over previous
#include <cuda_runtime.h>
#include <cuda_fp16.h>
#include <cstdint>

#define T_TOK 8192
#define DIM   1024
#define HID   4096
#define NEXP  8
#define BM 128
#define BN 128
#define BK 32
#define NMPAD  136
#define MAXPAD (NMPAD * BM)

#define SAH 40                     // smem row stride in halves (80 bytes)
#define ATILEH (BM * SAH)          // 5120 halves per tile
#define STGB (2 * ATILEH * 2)      // 20480 bytes per stage (A+B)
#define NSTG 4
#define SMEM_DYN (NSTG * STGB)     // 81920 bytes

// ---------------- scratch ----------------
__device__ __half g_gh[(size_t)MAXPAD * HID];      // raw gate g in fp16
__device__ __half g_hh[(size_t)MAXPAD * HID];      // h = silu(g)*u in fp16
__device__ __half g_xh[(size_t)T_TOK * DIM];       // x in fp16
__device__ __half g_wgT[(size_t)NEXP * HID * DIM]; // w_gate^T [e][n][k] fp16
__device__ __half g_wuT[(size_t)NEXP * HID * DIM];
__device__ __half g_wdT[(size_t)NEXP * DIM * HID];
__device__ int    g_perm[MAXPAD];
__device__ float  g_permw[MAXPAD];
__device__ int    g_offpad[NEXP + 1];
__device__ int    g_cnt[NEXP];
__device__ int    g_cursor[NEXP];
__device__ float  g_probsum[NEXP];
__device__ int    g_topi[T_TOK * 2];
__device__ float  g_topw[T_TOK * 2];

// ---------------- helpers ----------------
__device__ __forceinline__ uint32_t smem_u32(const void* p) {
    uint32_t a;
    asm("{ .reg .u64 t; cvta.to.shared.u64 t, %1; cvt.u32.u64 %0, t; }"
        : "=r"(a) : "l"(p));
    return a;
}
__device__ __forceinline__ void cp16h(uint32_t d, const __half* s, uint32_t sz) {
    asm volatile("cp.async.cg.shared.global [%0], [%1], 16, %2;"
                 :: "r"(d), "l"(s), "r"(sz));
}
#define CP_COMMIT() asm volatile("cp.async.commit_group;" ::: "memory")
#define CP_WAIT2()  asm volatile("cp.async.wait_group 2;" ::: "memory")

__device__ __forceinline__ void mma_f16(float* c, const uint32_t* a,
                                        const uint32_t* b) {
    asm volatile(
        "mma.sync.aligned.m16n8k16.row.col.f32.f16.f16.f32 "
        "{%0,%1,%2,%3}, {%4,%5,%6,%7}, {%8,%9}, {%0,%1,%2,%3};"
        : "+f"(c[0]), "+f"(c[1]), "+f"(c[2]), "+f"(c[3])
        : "r"(a[0]), "r"(a[1]), "r"(a[2]), "r"(a[3]), "r"(b[0]), "r"(b[1]));
}

__device__ __forceinline__ void ldsm_x4(uint32_t* r, uint32_t addr) {
    asm volatile("ldmatrix.sync.aligned.m8n8.x4.shared.b16 {%0,%1,%2,%3}, [%4];"
                 : "=r"(r[0]), "=r"(r[1]), "=r"(r[2]), "=r"(r[3]) : "r"(addr));
}

// ---------------- small kernels ----------------
__global__ void k_init() {
    int i = blockIdx.x * blockDim.x + threadIdx.x;
    if (i < NEXP) { g_cnt[i] = 0; g_cursor[i] = 0; g_probsum[i] = 0.f; }
    if (i < MAXPAD) g_perm[i] = -1;
}

__global__ void k_zero_out(float4* out, int n4) {
    float4 z = make_float4(0.f, 0.f, 0.f, 0.f);
    for (int i = blockIdx.x * blockDim.x + threadIdx.x; i < n4;
         i += gridDim.x * blockDim.x)
        out[i] = z;
}

// transpose+convert: src fp32 [e][R][C] -> dst fp16 [e][C][R], 64x64 tiles,
// float2 loads + half2 (128B-row) stores.
__global__ void k_tr(const float* __restrict__ src, int R, int C, int sel) {
    __half* dstb = (sel == 0) ? g_wgT : (sel == 1) ? g_wuT : g_wdT;
    __shared__ float t[64][65];
    size_t mo = (size_t)blockIdx.z * R * C;
    const float* s = src + mo;
    __half* d = dstb + mo;
    int c0 = blockIdx.x * 64, r0 = blockIdx.y * 64;
    int tx = threadIdx.x, ty = threadIdx.y;
#pragma unroll
    for (int j = ty; j < 64; j += 8) {
        float2 v = *(const float2*)&s[(size_t)(r0 + j) * C + c0 + tx * 2];
        t[j][tx * 2] = v.x; t[j][tx * 2 + 1] = v.y;
    }
    __syncthreads();
#pragma unroll
    for (int j = ty; j < 64; j += 8) {
        __half2 h = __floats2half2_rn(t[tx * 2][j], t[tx * 2 + 1][j]);
        *(__half2*)&d[(size_t)(c0 + j) * R + r0 + tx * 2] = h;
    }
}

// gating + fused x->fp16 conversion
__global__ void k_gate(const float* __restrict__ x, const float* __restrict__ gw) {
    int gwarp = (blockIdx.x * blockDim.x + threadIdx.x) >> 5;
    int lane  = threadIdx.x & 31;
    if (gwarp >= T_TOK) return;
    const float* xr = x + (size_t)gwarp * DIM;
    __half* xh = g_xh + (size_t)gwarp * DIM;

    float acc[NEXP];
#pragma unroll
    for (int e = 0; e < NEXP; e++) acc[e] = 0.f;
    for (int i = lane; i < DIM; i += 32) {
        float xv = xr[i];
        xh[i] = __float2half_rn(xv);
        float4 g0 = *(const float4*)(gw + (size_t)i * NEXP);
        float4 g1 = *(const float4*)(gw + (size_t)i * NEXP + 4);
        acc[0] += xv * g0.x; acc[1] += xv * g0.y;
        acc[2] += xv * g0.z; acc[3] += xv * g0.w;
        acc[4] += xv * g1.x; acc[5] += xv * g1.y;
        acc[6] += xv * g1.z; acc[7] += xv * g1.w;
    }
#pragma unroll
    for (int off = 16; off > 0; off >>= 1)
#pragma unroll
        for (int e = 0; e < NEXP; e++)
            acc[e] += __shfl_xor_sync(0xffffffffu, acc[e], off);

    float mx = acc[0];
#pragma unroll
    for (int e = 1; e < NEXP; e++) mx = fmaxf(mx, acc[e]);
    float p[NEXP], s = 0.f;
#pragma unroll
    for (int e = 0; e < NEXP; e++) { p[e] = __expf(acc[e] - mx); s += p[e]; }
    float inv = 1.f / s;
    if (lane < NEXP) atomicAdd(&g_probsum[lane], p[lane] * inv);

    if (lane == 0) {
        int i0 = 0;
#pragma unroll
        for (int e = 1; e < NEXP; e++) if (acc[e] > acc[i0]) i0 = e;
        int i1 = (i0 == 0) ? 1 : 0;
#pragma unroll
        for (int e = 0; e < NEXP; e++)
            if (e != i0 && acc[e] > acc[i1]) i1 = e;
        float m2 = fmaxf(acc[i0], acc[i1]);
        float e0 = __expf(acc[i0] - m2), e1 = __expf(acc[i1] - m2);
        float inv2 = 1.f / (e0 + e1);
        g_topi[2 * gwarp]     = i0; g_topw[2 * gwarp]     = e0 * inv2;
        g_topi[2 * gwarp + 1] = i1; g_topw[2 * gwarp + 1] = e1 * inv2;
        atomicAdd(&g_cnt[i0], 1);
        atomicAdd(&g_cnt[i1], 1);
    }
}

__global__ void k_offsets(float* __restrict__ out) {
    if (threadIdx.x != 0 || blockIdx.x != 0) return;
    int off = 0;
    for (int e = 0; e < NEXP; e++) {
        g_offpad[e] = off;
        off += ((g_cnt[e] + BM - 1) / BM) * BM;
    }
    g_offpad[NEXP] = off;
    float loss = 0.f;
    const float invT = 1.f / (float)T_TOK;
    for (int e = 0; e < NEXP; e++) {
        float m = g_probsum[e] * invT;
        out[(size_t)T_TOK * DIM + 1 + e] = m;
        loss += m * m;
    }
    out[(size_t)T_TOK * DIM] = (float)NEXP * loss;
}

__global__ void k_scatter() {
    int t = blockIdx.x * blockDim.x + threadIdx.x;
    if (t >= 2 * T_TOK) return;
    int e = g_topi[t];
    int pos = g_offpad[e] + atomicAdd(&g_cursor[e], 1);
    g_perm[pos]  = t >> 1;
    g_permw[pos] = g_topw[t];
}

// ---------------- GEMM1 core (gate or up), fp16 MMA, 4-stage ----------------
template<int UP>
__device__ __forceinline__ void gemm1_body(const __half* __restrict__ wT) {
    extern __shared__ __half smh[];
    int total = g_offpad[NEXP];
    int mbase = blockIdx.y * BM;
    if (mbase >= total) return;
    int e = 0;
#pragma unroll
    for (int i = 0; i < NEXP; i++) if (mbase >= g_offpad[i + 1]) e = i + 1;

    const __half* W = wT + (size_t)e * DIM * HID;   // [n=HID][k=DIM]
    int ncol = blockIdx.x * BN;

    int tid = threadIdx.x;
    uint32_t smb = smem_u32(smh);

    int chk = (tid & 3) * 8;
    uint32_t adst[2], bdst[2];
    const __half *asrc[2], *bsrc[2];
    uint32_t asz[2];
#pragma unroll
    for (int p = 0; p < 2; p++) {
        int row = (tid >> 2) + p * 64;
        adst[p] = (uint32_t)((row * SAH + chk) * 2);
        bdst[p] = (uint32_t)((ATILEH + row * SAH + chk) * 2);
        int tok = g_perm[mbase + row];
        asrc[p] = g_xh + ((tok >= 0) ? (size_t)tok * DIM : 0) + chk;
        asz[p]  = (tok >= 0) ? 16u : 0u;
        bsrc[p] = W + (size_t)(ncol + row) * DIM + chk;
    }

    int lane = tid & 31, gid = lane >> 2, tig = lane & 3;
    int wm = (tid >> 5) & 3, wn = tid >> 7;
    uint32_t aln = (uint32_t)(((wm * 32 + (lane & 15)) * SAH + (lane >> 4) * 8) * 2);
    uint32_t bln = (uint32_t)((ATILEH +
        (wn * 64 + (lane & 7) + ((lane >> 4) << 3)) * SAH +
        ((lane >> 3) & 1) * 8) * 2);

    float acc[2][8][4];
#pragma unroll
    for (int mt = 0; mt < 2; mt++)
#pragma unroll
        for (int nt = 0; nt < 8; nt++)
#pragma unroll
            for (int q = 0; q < 4; q++) acc[mt][nt][q] = 0.f;

    const int NT = DIM / BK;             // 32
#pragma unroll
    for (int t = 0; t < 3; t++) {        // prologue: 3 stages
        uint32_t base = smb + t * STGB;
        int k0 = t * BK;
#pragma unroll
        for (int p = 0; p < 2; p++) cp16h(base + adst[p], asrc[p] + k0, asz[p]);
#pragma unroll
        for (int p = 0; p < 2; p++) cp16h(base + bdst[p], bsrc[p] + k0, 16);
        CP_COMMIT();
    }

    for (int i = 0; i < NT; i++) {
        CP_WAIT2();
        __syncthreads();
        int t = i + 3;
        if (t < NT) {
            uint32_t base = smb + (t % NSTG) * STGB;
            int k0 = t * BK;
#pragma unroll
            for (int p = 0; p < 2; p++) cp16h(base + adst[p], asrc[p] + k0, asz[p]);
#pragma unroll
            for (int p = 0; p < 2; p++) cp16h(base + bdst[p], bsrc[p] + k0, 16);
        }
        CP_COMMIT();

        uint32_t stg = smb + (uint32_t)(i % NSTG) * STGB;
#pragma unroll
        for (int ks = 0; ks < 2; ks++) {
            uint32_t a[2][4], b[4][4];
#pragma unroll
            for (int mt = 0; mt < 2; mt++)
                ldsm_x4(a[mt], stg + aln + (uint32_t)(mt * 16 * SAH * 2 + ks * 32));
#pragma unroll
            for (int j = 0; j < 4; j++)
                ldsm_x4(b[j], stg + bln + (uint32_t)(j * 16 * SAH * 2 + ks * 32));
#pragma unroll
            for (int mt = 0; mt < 2; mt++)
#pragma unroll
                for (int j = 0; j < 4; j++) {
                    mma_f16(acc[mt][2 * j],     a[mt], &b[j][0]);
                    mma_f16(acc[mt][2 * j + 1], a[mt], &b[j][2]);
                }
        }
    }

#pragma unroll
    for (int mt = 0; mt < 2; mt++) {
        int r = mbase + wm * 32 + mt * 16 + gid;
#pragma unroll
        for (int nt = 0; nt < 8; nt++) {
            int c = ncol + wn * 64 + nt * 8 + 2 * tig;
            if (UP) {
                float2 ga = __half22float2(*(__half2*)&g_gh[(size_t)r * HID + c]);
                float2 gb = __half22float2(*(__half2*)&g_gh[(size_t)(r + 8) * HID + c]);
                float h0 = ga.x * (1.f / (1.f + __expf(-ga.x))) * acc[mt][nt][0];
                float h1 = ga.y * (1.f / (1.f + __expf(-ga.y))) * acc[mt][nt][1];
                float h2 = gb.x * (1.f / (1.f + __expf(-gb.x))) * acc[mt][nt][2];
                float h3 = gb.y * (1.f / (1.f + __expf(-gb.y))) * acc[mt][nt][3];
                *(__half2*)&g_hh[(size_t)r * HID + c]       = __floats2half2_rn(h0, h1);
                *(__half2*)&g_hh[(size_t)(r + 8) * HID + c] = __floats2half2_rn(h2, h3);
            } else {
                *(__half2*)&g_gh[(size_t)r * HID + c] =
                    __floats2half2_rn(acc[mt][nt][0], acc[mt][nt][1]);
                *(__half2*)&g_gh[(size_t)(r + 8) * HID + c] =
                    __floats2half2_rn(acc[mt][nt][2], acc[mt][nt][3]);
            }
        }
    }
}

__global__ __launch_bounds__(256) void k_g1gate() { gemm1_body<0>(g_wgT); }
__global__ __launch_bounds__(256) void k_g1up()   { gemm1_body<1>(g_wuT); }

// ---------------- GEMM2: A = g_hh fp16, B = g_wdT fp16, atomic epilogue --------
__global__ __launch_bounds__(256) void k_gemm2_mma(float* __restrict__ out) {
    extern __shared__ __half smh[];
    int total = g_offpad[NEXP];
    int mbase = blockIdx.y * BM;
    if (mbase >= total) return;
    int e = 0;
#pragma unroll
    for (int i = 0; i < NEXP; i++) if (mbase >= g_offpad[i + 1]) e = i + 1;

    const __half* W = g_wdT + (size_t)e * DIM * HID;   // [n=DIM][k=HID]
    int ncol = blockIdx.x * BN;

    int tid = threadIdx.x;
    uint32_t smb = smem_u32(smh);

    int chk = (tid & 3) * 8;
    uint32_t adst[2], bdst[2];
    const __half *asrc[2], *bsrc[2];
#pragma unroll
    for (int p = 0; p < 2; p++) {
        int row = (tid >> 2) + p * 64;
        adst[p] = (uint32_t)((row * SAH + chk) * 2);
        bdst[p] = (uint32_t)((ATILEH + row * SAH + chk) * 2);
        asrc[p] = g_hh + (size_t)(mbase + row) * HID + chk;
        bsrc[p] = W + (size_t)(ncol + row) * HID + chk;
    }

    int lane = tid & 31, gid = lane >> 2, tig = lane & 3;
    int wm = (tid >> 5) & 3, wn = tid >> 7;
    uint32_t aln = (uint32_t)(((wm * 32 + (lane & 15)) * SAH + (lane >> 4) * 8) * 2);
    uint32_t bln = (uint32_t)((ATILEH +
        (wn * 64 + (lane & 7) + ((lane >> 4) << 3)) * SAH +
        ((lane >> 3) & 1) * 8) * 2);

    float acc[2][8][4];
#pragma unroll
    for (int mt = 0; mt < 2; mt++)
#pragma unroll
        for (int nt = 0; nt < 8; nt++)
#pragma unroll
            for (int q = 0; q < 4; q++) acc[mt][nt][q] = 0.f;

    const int NT = HID / BK;            // 128
#pragma unroll
    for (int t = 0; t < 3; t++) {
        uint32_t base = smb + t * STGB;
        int k0 = t * BK;
#pragma unroll
        for (int p = 0; p < 2; p++) cp16h(base + adst[p], asrc[p] + k0, 16);
#pragma unroll
        for (int p = 0; p < 2; p++) cp16h(base + bdst[p], bsrc[p] + k0, 16);
        CP_COMMIT();
    }

    for (int i = 0; i < NT; i++) {
        CP_WAIT2();
        __syncthreads();
        int t = i + 3;
        if (t < NT) {
            uint32_t base = smb + (t % NSTG) * STGB;
            int k0 = t * BK;
#pragma unroll
            for (int p = 0; p < 2; p++) cp16h(base + adst[p], asrc[p] + k0, 16);
#pragma unroll
            for (int p = 0; p < 2; p++) cp16h(base + bdst[p], bsrc[p] + k0, 16);
        }
        CP_COMMIT();

        uint32_t stg = smb + (uint32_t)(i % NSTG) * STGB;
#pragma unroll
        for (int ks = 0; ks < 2; ks++) {
            uint32_t a[2][4], b[4][4];
#pragma unroll
            for (int mt = 0; mt < 2; mt++)
                ldsm_x4(a[mt], stg + aln + (uint32_t)(mt * 16 * SAH * 2 + ks * 32));
#pragma unroll
            for (int j = 0; j < 4; j++)
                ldsm_x4(b[j], stg + bln + (uint32_t)(j * 16 * SAH * 2 + ks * 32));
#pragma unroll
            for (int mt = 0; mt < 2; mt++)
#pragma unroll
                for (int j = 0; j < 4; j++) {
                    mma_f16(acc[mt][2 * j],     a[mt], &b[j][0]);
                    mma_f16(acc[mt][2 * j + 1], a[mt], &b[j][2]);
                }
        }
    }

#pragma unroll
    for (int mt = 0; mt < 2; mt++) {
        int slot = mbase + wm * 32 + mt * 16 + gid;
        int tok0 = g_perm[slot],     tok1 = g_perm[slot + 8];
        float w0 = g_permw[slot],    w1 = g_permw[slot + 8];
#pragma unroll
        for (int nt = 0; nt < 8; nt++) {
            int c = ncol + wn * 64 + nt * 8 + 2 * tig;
            if (tok0 >= 0) {
                float* op = out + (size_t)tok0 * DIM + c;
                atomicAdd(op,     w0 * acc[mt][nt][0]);
                atomicAdd(op + 1, w0 * acc[mt][nt][1]);
            }
            if (tok1 >= 0) {
                float* op = out + (size_t)tok1 * DIM + c;
                atomicAdd(op,     w1 * acc[mt][nt][2]);
                atomicAdd(op + 1, w1 * acc[mt][nt][3]);
            }
        }
    }
}

// ---------------- launch ----------------
extern "C" void kernel_launch(void* const* d_in, const int* in_sizes, int n_in,
                              void* d_out, int out_size) {
    const float* x      = (const float*)d_in[0];
    const float* gate_w = (const float*)d_in[1];
    const float* w_gate = (const float*)d_in[2];
    const float* w_up   = (const float*)d_in[3];
    const float* w_down = (const float*)d_in[4];
    float* out = (float*)d_out;

    cudaFuncSetAttribute(k_g1gate, cudaFuncAttributeMaxDynamicSharedMemorySize,
                         SMEM_DYN);
    cudaFuncSetAttribute(k_g1up, cudaFuncAttributeMaxDynamicSharedMemorySize,
                         SMEM_DYN);
    cudaFuncSetAttribute(k_gemm2_mma, cudaFuncAttributeMaxDynamicSharedMemorySize,
                         SMEM_DYN);

    k_init<<<MAXPAD / 256, 256>>>();
    k_zero_out<<<2048, 256>>>((float4*)out, (T_TOK * DIM) / 4);
    k_gate<<<T_TOK / 8, 256>>>(x, gate_w);
    k_offsets<<<1, 32>>>(out);
    k_scatter<<<(2 * T_TOK) / 256, 256>>>();

    dim3 trb(32, 8);
    k_tr<<<dim3(HID / 64, DIM / 64, NEXP), trb>>>(w_gate, DIM, HID, 0);
    k_tr<<<dim3(HID / 64, DIM / 64, NEXP), trb>>>(w_up,   DIM, HID, 1);
    k_tr<<<dim3(DIM / 64, HID / 64, NEXP), trb>>>(w_down, HID, DIM, 2);

    k_g1gate<<<dim3(HID / BN, NMPAD), 256, SMEM_DYN>>>();
    k_g1up<<<dim3(HID / BN, NMPAD), 256, SMEM_DYN>>>();
    k_gemm2_mma<<<dim3(DIM / BN, NMPAD), 256, SMEM_DYN>>>(out);
}

// round 12
// speedup vs baseline: 1.5977x; 1.0200x over previous
#include <cuda_runtime.h>
#include <cuda_fp16.h>
#include <cstdint>

#define T_TOK 8192
#define DIM   1024
#define HID   4096
#define NEXP  8
#define BM 128
#define BN 128
#define BK 32
#define NMPAD  136
#define MAXPAD (NMPAD * BM)

#define SAH 40                     // smem row stride in halves (80 bytes)
#define ATILEH (BM * SAH)          // 5120 halves per tile
#define STGB (2 * ATILEH * 2)      // 20480 bytes per stage (A+B)
#define NSTG 4
#define SMEM_DYN (NSTG * STGB)     // 81920 bytes

// ---------------- scratch ----------------
__device__ __half g_gh[(size_t)MAXPAD * HID];      // raw gate g in fp16
__device__ __half g_hh[(size_t)MAXPAD * HID];      // h = silu(g)*u in fp16
__device__ __half g_xh[(size_t)T_TOK * DIM];       // x in fp16
__device__ __half g_wgT[(size_t)NEXP * HID * DIM]; // w_gate^T [e][n][k] fp16
__device__ __half g_wuT[(size_t)NEXP * HID * DIM];
__device__ __half g_wdT[(size_t)NEXP * DIM * HID];
__device__ int    g_perm[MAXPAD];
__device__ float  g_permw[MAXPAD];
__device__ int    g_offpad[NEXP + 1];
__device__ int    g_cnt[NEXP];
__device__ int    g_cursor[NEXP];
__device__ float  g_probsum[NEXP];
__device__ int    g_topi[T_TOK * 2];
__device__ float  g_topw[T_TOK * 2];

// ---------------- helpers ----------------
__device__ __forceinline__ uint32_t smem_u32(const void* p) {
    uint32_t a;
    asm("{ .reg .u64 t; cvta.to.shared.u64 t, %1; cvt.u32.u64 %0, t; }"
        : "=r"(a) : "l"(p));
    return a;
}
__device__ __forceinline__ void cp16h(uint32_t d, const __half* s, uint32_t sz) {
    asm volatile("cp.async.cg.shared.global [%0], [%1], 16, %2;"
                 :: "r"(d), "l"(s), "r"(sz));
}
#define CP_COMMIT() asm volatile("cp.async.commit_group;" ::: "memory")
#define CP_WAIT2()  asm volatile("cp.async.wait_group 2;" ::: "memory")

__device__ __forceinline__ void mma_f16(float* c, const uint32_t* a,
                                        const uint32_t* b) {
    asm volatile(
        "mma.sync.aligned.m16n8k16.row.col.f32.f16.f16.f32 "
        "{%0,%1,%2,%3}, {%4,%5,%6,%7}, {%8,%9}, {%0,%1,%2,%3};"
        : "+f"(c[0]), "+f"(c[1]), "+f"(c[2]), "+f"(c[3])
        : "r"(a[0]), "r"(a[1]), "r"(a[2]), "r"(a[3]), "r"(b[0]), "r"(b[1]));
}

__device__ __forceinline__ void ldsm_x4(uint32_t* r, uint32_t addr) {
    asm volatile("ldmatrix.sync.aligned.m8n8.x4.shared.b16 {%0,%1,%2,%3}, [%4];"
                 : "=r"(r[0]), "=r"(r[1]), "=r"(r[2]), "=r"(r[3]) : "r"(addr));
}

// ---------------- small kernels ----------------
__global__ void k_init() {
    int i = blockIdx.x * blockDim.x + threadIdx.x;
    if (i < NEXP) { g_cnt[i] = 0; g_cursor[i] = 0; g_probsum[i] = 0.f; }
    if (i < MAXPAD) g_perm[i] = -1;
}

__global__ void k_zero_out(float4* out, int n4) {
    float4 z = make_float4(0.f, 0.f, 0.f, 0.f);
    for (int i = blockIdx.x * blockDim.x + threadIdx.x; i < n4;
         i += gridDim.x * blockDim.x)
        out[i] = z;
}

// transpose+convert: src fp32 [e][R][C] -> dst fp16 [e][C][R], 64x64 tiles
__global__ void k_tr(const float* __restrict__ src, int R, int C, int sel) {
    __half* dstb = (sel == 0) ? g_wgT : (sel == 1) ? g_wuT : g_wdT;
    __shared__ float t[64][65];
    size_t mo = (size_t)blockIdx.z * R * C;
    const float* s = src + mo;
    __half* d = dstb + mo;
    int c0 = blockIdx.x * 64, r0 = blockIdx.y * 64;
    int tx = threadIdx.x, ty = threadIdx.y;
#pragma unroll
    for (int j = ty; j < 64; j += 8) {
        float2 v = *(const float2*)&s[(size_t)(r0 + j) * C + c0 + tx * 2];
        t[j][tx * 2] = v.x; t[j][tx * 2 + 1] = v.y;
    }
    __syncthreads();
#pragma unroll
    for (int j = ty; j < 64; j += 8) {
        __half2 h = __floats2half2_rn(t[tx * 2][j], t[tx * 2 + 1][j]);
        *(__half2*)&d[(size_t)(c0 + j) * R + r0 + tx * 2] = h;
    }
}

// gating + fused x->fp16 conversion
__global__ void k_gate(const float* __restrict__ x, const float* __restrict__ gw) {
    int gwarp = (blockIdx.x * blockDim.x + threadIdx.x) >> 5;
    int lane  = threadIdx.x & 31;
    if (gwarp >= T_TOK) return;
    const float* xr = x + (size_t)gwarp * DIM;
    __half* xh = g_xh + (size_t)gwarp * DIM;

    float acc[NEXP];
#pragma unroll
    for (int e = 0; e < NEXP; e++) acc[e] = 0.f;
    for (int i = lane; i < DIM; i += 32) {
        float xv = xr[i];
        xh[i] = __float2half_rn(xv);
        float4 g0 = *(const float4*)(gw + (size_t)i * NEXP);
        float4 g1 = *(const float4*)(gw + (size_t)i * NEXP + 4);
        acc[0] += xv * g0.x; acc[1] += xv * g0.y;
        acc[2] += xv * g0.z; acc[3] += xv * g0.w;
        acc[4] += xv * g1.x; acc[5] += xv * g1.y;
        acc[6] += xv * g1.z; acc[7] += xv * g1.w;
    }
#pragma unroll
    for (int off = 16; off > 0; off >>= 1)
#pragma unroll
        for (int e = 0; e < NEXP; e++)
            acc[e] += __shfl_xor_sync(0xffffffffu, acc[e], off);

    float mx = acc[0];
#pragma unroll
    for (int e = 1; e < NEXP; e++) mx = fmaxf(mx, acc[e]);
    float p[NEXP], s = 0.f;
#pragma unroll
    for (int e = 0; e < NEXP; e++) { p[e] = __expf(acc[e] - mx); s += p[e]; }
    float inv = 1.f / s;
    if (lane < NEXP) atomicAdd(&g_probsum[lane], p[lane] * inv);

    if (lane == 0) {
        int i0 = 0;
#pragma unroll
        for (int e = 1; e < NEXP; e++) if (acc[e] > acc[i0]) i0 = e;
        int i1 = (i0 == 0) ? 1 : 0;
#pragma unroll
        for (int e = 0; e < NEXP; e++)
            if (e != i0 && acc[e] > acc[i1]) i1 = e;
        float m2 = fmaxf(acc[i0], acc[i1]);
        float e0 = __expf(acc[i0] - m2), e1 = __expf(acc[i1] - m2);
        float inv2 = 1.f / (e0 + e1);
        g_topi[2 * gwarp]     = i0; g_topw[2 * gwarp]     = e0 * inv2;
        g_topi[2 * gwarp + 1] = i1; g_topw[2 * gwarp + 1] = e1 * inv2;
        atomicAdd(&g_cnt[i0], 1);
        atomicAdd(&g_cnt[i1], 1);
    }
}

__global__ void k_offsets(float* __restrict__ out) {
    if (threadIdx.x != 0 || blockIdx.x != 0) return;
    int off = 0;
    for (int e = 0; e < NEXP; e++) {
        g_offpad[e] = off;
        off += ((g_cnt[e] + BM - 1) / BM) * BM;
    }
    g_offpad[NEXP] = off;
    float loss = 0.f;
    const float invT = 1.f / (float)T_TOK;
    for (int e = 0; e < NEXP; e++) {
        float m = g_probsum[e] * invT;
        out[(size_t)T_TOK * DIM + 1 + e] = m;
        loss += m * m;
    }
    out[(size_t)T_TOK * DIM] = (float)NEXP * loss;
}

__global__ void k_scatter() {
    int t = blockIdx.x * blockDim.x + threadIdx.x;
    if (t >= 2 * T_TOK) return;
    int e = g_topi[t];
    int pos = g_offpad[e] + atomicAdd(&g_cursor[e], 1);
    g_perm[pos]  = t >> 1;
    g_permw[pos] = g_topw[t];
}

// ---------------- GEMM1 core (gate or up), fp16 MMA, 4-stage ----------------
template<int UP>
__device__ __forceinline__ void gemm1_body(const __half* __restrict__ wT) {
    extern __shared__ __half smh[];
    int total = g_offpad[NEXP];
    int mbase = blockIdx.y * BM;
    if (mbase >= total) return;
    int e = 0;
#pragma unroll
    for (int i = 0; i < NEXP; i++) if (mbase >= g_offpad[i + 1]) e = i + 1;

    const __half* W = wT + (size_t)e * DIM * HID;   // [n=HID][k=DIM]
    int ncol = blockIdx.x * BN;

    int tid = threadIdx.x;
    uint32_t smb = smem_u32(smh);

    int chk = (tid & 3) * 8;
    uint32_t adst[2], bdst[2];
    const __half *asrc[2], *bsrc[2];
    uint32_t asz[2];
#pragma unroll
    for (int p = 0; p < 2; p++) {
        int row = (tid >> 2) + p * 64;
        adst[p] = (uint32_t)((row * SAH + chk) * 2);
        bdst[p] = (uint32_t)((ATILEH + row * SAH + chk) * 2);
        int tok = g_perm[mbase + row];
        asrc[p] = g_xh + ((tok >= 0) ? (size_t)tok * DIM : 0) + chk;
        asz[p]  = (tok >= 0) ? 16u : 0u;
        bsrc[p] = W + (size_t)(ncol + row) * DIM + chk;
    }

    int lane = tid & 31, gid = lane >> 2, tig = lane & 3;
    int wm = (tid >> 5) & 3, wn = tid >> 7;
    uint32_t aln = (uint32_t)(((wm * 32 + (lane & 15)) * SAH + (lane >> 4) * 8) * 2);
    uint32_t bln = (uint32_t)((ATILEH +
        (wn * 64 + (lane & 7) + ((lane >> 4) << 3)) * SAH +
        ((lane >> 3) & 1) * 8) * 2);

    float acc[2][8][4];
#pragma unroll
    for (int mt = 0; mt < 2; mt++)
#pragma unroll
        for (int nt = 0; nt < 8; nt++)
#pragma unroll
            for (int q = 0; q < 4; q++) acc[mt][nt][q] = 0.f;

    const int NT = DIM / BK;             // 32
#pragma unroll
    for (int t = 0; t < 3; t++) {
        uint32_t base = smb + t * STGB;
        int k0 = t * BK;
#pragma unroll
        for (int p = 0; p < 2; p++) cp16h(base + adst[p], asrc[p] + k0, asz[p]);
#pragma unroll
        for (int p = 0; p < 2; p++) cp16h(base + bdst[p], bsrc[p] + k0, 16);
        CP_COMMIT();
    }

    for (int i = 0; i < NT; i++) {
        CP_WAIT2();
        __syncthreads();
        int t = i + 3;
        if (t < NT) {
            uint32_t base = smb + (t % NSTG) * STGB;
            int k0 = t * BK;
#pragma unroll
            for (int p = 0; p < 2; p++) cp16h(base + adst[p], asrc[p] + k0, asz[p]);
#pragma unroll
            for (int p = 0; p < 2; p++) cp16h(base + bdst[p], bsrc[p] + k0, 16);
        }
        CP_COMMIT();

        uint32_t stg = smb + (uint32_t)(i % NSTG) * STGB;
#pragma unroll
        for (int ks = 0; ks < 2; ks++) {
            uint32_t a[2][4], b[4][4];
#pragma unroll
            for (int mt = 0; mt < 2; mt++)
                ldsm_x4(a[mt], stg + aln + (uint32_t)(mt * 16 * SAH * 2 + ks * 32));
#pragma unroll
            for (int j = 0; j < 4; j++)
                ldsm_x4(b[j], stg + bln + (uint32_t)(j * 16 * SAH * 2 + ks * 32));
#pragma unroll
            for (int mt = 0; mt < 2; mt++)
#pragma unroll
                for (int j = 0; j < 4; j++) {
                    mma_f16(acc[mt][2 * j],     a[mt], &b[j][0]);
                    mma_f16(acc[mt][2 * j + 1], a[mt], &b[j][2]);
                }
        }
    }

#pragma unroll
    for (int mt = 0; mt < 2; mt++) {
        int r = mbase + wm * 32 + mt * 16 + gid;
#pragma unroll
        for (int nt = 0; nt < 8; nt++) {
            int c = ncol + wn * 64 + nt * 8 + 2 * tig;
            if (UP) {
                float2 ga = __half22float2(*(__half2*)&g_gh[(size_t)r * HID + c]);
                float2 gb = __half22float2(*(__half2*)&g_gh[(size_t)(r + 8) * HID + c]);
                float h0 = ga.x * (1.f / (1.f + __expf(-ga.x))) * acc[mt][nt][0];
                float h1 = ga.y * (1.f / (1.f + __expf(-ga.y))) * acc[mt][nt][1];
                float h2 = gb.x * (1.f / (1.f + __expf(-gb.x))) * acc[mt][nt][2];
                float h3 = gb.y * (1.f / (1.f + __expf(-gb.y))) * acc[mt][nt][3];
                *(__half2*)&g_hh[(size_t)r * HID + c]       = __floats2half2_rn(h0, h1);
                *(__half2*)&g_hh[(size_t)(r + 8) * HID + c] = __floats2half2_rn(h2, h3);
            } else {
                *(__half2*)&g_gh[(size_t)r * HID + c] =
                    __floats2half2_rn(acc[mt][nt][0], acc[mt][nt][1]);
                *(__half2*)&g_gh[(size_t)(r + 8) * HID + c] =
                    __floats2half2_rn(acc[mt][nt][2], acc[mt][nt][3]);
            }
        }
    }
}

__global__ __launch_bounds__(256) void k_g1gate() { gemm1_body<0>(g_wgT); }
__global__ __launch_bounds__(256) void k_g1up()   { gemm1_body<1>(g_wuT); }

// ---------------- GEMM2: A = g_hh fp16, B = g_wdT fp16, atomic epilogue --------
__global__ __launch_bounds__(256) void k_gemm2_mma(float* __restrict__ out) {
    extern __shared__ __half smh[];
    int total = g_offpad[NEXP];
    int mbase = blockIdx.y * BM;
    if (mbase >= total) return;
    int e = 0;
#pragma unroll
    for (int i = 0; i < NEXP; i++) if (mbase >= g_offpad[i + 1]) e = i + 1;

    const __half* W = g_wdT + (size_t)e * DIM * HID;   // [n=DIM][k=HID]
    int ncol = blockIdx.x * BN;

    int tid = threadIdx.x;
    uint32_t smb = smem_u32(smh);

    int chk = (tid & 3) * 8;
    uint32_t adst[2], bdst[2];
    const __half *asrc[2], *bsrc[2];
#pragma unroll
    for (int p = 0; p < 2; p++) {
        int row = (tid >> 2) + p * 64;
        adst[p] = (uint32_t)((row * SAH + chk) * 2);
        bdst[p] = (uint32_t)((ATILEH + row * SAH + chk) * 2);
        asrc[p] = g_hh + (size_t)(mbase + row) * HID + chk;
        bsrc[p] = W + (size_t)(ncol + row) * HID + chk;
    }

    int lane = tid & 31, gid = lane >> 2, tig = lane & 3;
    int wm = (tid >> 5) & 3, wn = tid >> 7;
    uint32_t aln = (uint32_t)(((wm * 32 + (lane & 15)) * SAH + (lane >> 4) * 8) * 2);
    uint32_t bln = (uint32_t)((ATILEH +
        (wn * 64 + (lane & 7) + ((lane >> 4) << 3)) * SAH +
        ((lane >> 3) & 1) * 8) * 2);

    float acc[2][8][4];
#pragma unroll
    for (int mt = 0; mt < 2; mt++)
#pragma unroll
        for (int nt = 0; nt < 8; nt++)
#pragma unroll
            for (int q = 0; q < 4; q++) acc[mt][nt][q] = 0.f;

    const int NT = HID / BK;            // 128
#pragma unroll
    for (int t = 0; t < 3; t++) {
        uint32_t base = smb + t * STGB;
        int k0 = t * BK;
#pragma unroll
        for (int p = 0; p < 2; p++) cp16h(base + adst[p], asrc[p] + k0, 16);
#pragma unroll
        for (int p = 0; p < 2; p++) cp16h(base + bdst[p], bsrc[p] + k0, 16);
        CP_COMMIT();
    }

    for (int i = 0; i < NT; i++) {
        CP_WAIT2();
        __syncthreads();
        int t = i + 3;
        if (t < NT) {
            uint32_t base = smb + (t % NSTG) * STGB;
            int k0 = t * BK;
#pragma unroll
            for (int p = 0; p < 2; p++) cp16h(base + adst[p], asrc[p] + k0, 16);
#pragma unroll
            for (int p = 0; p < 2; p++) cp16h(base + bdst[p], bsrc[p] + k0, 16);
        }
        CP_COMMIT();

        uint32_t stg = smb + (uint32_t)(i % NSTG) * STGB;
#pragma unroll
        for (int ks = 0; ks < 2; ks++) {
            uint32_t a[2][4], b[4][4];
#pragma unroll
            for (int mt = 0; mt < 2; mt++)
                ldsm_x4(a[mt], stg + aln + (uint32_t)(mt * 16 * SAH * 2 + ks * 32));
#pragma unroll
            for (int j = 0; j < 4; j++)
                ldsm_x4(b[j], stg + bln + (uint32_t)(j * 16 * SAH * 2 + ks * 32));
#pragma unroll
            for (int mt = 0; mt < 2; mt++)
#pragma unroll
                for (int j = 0; j < 4; j++) {
                    mma_f16(acc[mt][2 * j],     a[mt], &b[j][0]);
                    mma_f16(acc[mt][2 * j + 1], a[mt], &b[j][2]);
                }
        }
    }

#pragma unroll
    for (int mt = 0; mt < 2; mt++) {
        int slot = mbase + wm * 32 + mt * 16 + gid;
        int tok0 = g_perm[slot],     tok1 = g_perm[slot + 8];
        float w0 = g_permw[slot],    w1 = g_permw[slot + 8];
#pragma unroll
        for (int nt = 0; nt < 8; nt++) {
            int c = ncol + wn * 64 + nt * 8 + 2 * tig;
            if (tok0 >= 0) {
                float* op = out + (size_t)tok0 * DIM + c;
                atomicAdd(op,     w0 * acc[mt][nt][0]);
                atomicAdd(op + 1, w0 * acc[mt][nt][1]);
            }
            if (tok1 >= 0) {
                float* op = out + (size_t)tok1 * DIM + c;
                atomicAdd(op,     w1 * acc[mt][nt][2]);
                atomicAdd(op + 1, w1 * acc[mt][nt][3]);
            }
        }
    }
}

// ---------------- launch: fork-join streams to overlap transposes ----------------
extern "C" void kernel_launch(void* const* d_in, const int* in_sizes, int n_in,
                              void* d_out, int out_size) {
    const float* x      = (const float*)d_in[0];
    const float* gate_w = (const float*)d_in[1];
    const float* w_gate = (const float*)d_in[2];
    const float* w_up   = (const float*)d_in[3];
    const float* w_down = (const float*)d_in[4];
    float* out = (float*)d_out;

    static bool inited = false;
    static cudaStream_t s1, s2;
    static cudaEvent_t eF, eWg, eWu, eWd, eZ;
    if (!inited) {
        cudaFuncSetAttribute(k_g1gate, cudaFuncAttributeMaxDynamicSharedMemorySize,
                             SMEM_DYN);
        cudaFuncSetAttribute(k_g1up, cudaFuncAttributeMaxDynamicSharedMemorySize,
                             SMEM_DYN);
        cudaFuncSetAttribute(k_gemm2_mma, cudaFuncAttributeMaxDynamicSharedMemorySize,
                             SMEM_DYN);
        cudaStreamCreateWithFlags(&s1, cudaStreamNonBlocking);
        cudaStreamCreateWithFlags(&s2, cudaStreamNonBlocking);
        cudaEventCreateWithFlags(&eF,  cudaEventDisableTiming);
        cudaEventCreateWithFlags(&eWg, cudaEventDisableTiming);
        cudaEventCreateWithFlags(&eWu, cudaEventDisableTiming);
        cudaEventCreateWithFlags(&eWd, cudaEventDisableTiming);
        cudaEventCreateWithFlags(&eZ,  cudaEventDisableTiming);
        inited = true;
    }

    // fork
    cudaEventRecord(eF, 0);
    cudaStreamWaitEvent(s1, eF, 0);
    cudaStreamWaitEvent(s2, eF, 0);

    // s1: weight transposes (independent of routing chain)
    dim3 trb(32, 8);
    k_tr<<<dim3(HID / 64, DIM / 64, NEXP), trb, 0, s1>>>(w_gate, DIM, HID, 0);
    cudaEventRecord(eWg, s1);
    k_tr<<<dim3(HID / 64, DIM / 64, NEXP), trb, 0, s1>>>(w_up,   DIM, HID, 1);
    cudaEventRecord(eWu, s1);
    k_tr<<<dim3(DIM / 64, HID / 64, NEXP), trb, 0, s1>>>(w_down, HID, DIM, 2);
    cudaEventRecord(eWd, s1);

    // s2: output zeroing (needed only by gemm2)
    k_zero_out<<<2048, 256, 0, s2>>>((float4*)out, (T_TOK * DIM) / 4);
    cudaEventRecord(eZ, s2);

    // main: routing chain
    k_init<<<MAXPAD / 256, 256>>>();
    k_gate<<<T_TOK / 8, 256>>>(x, gate_w);
    k_offsets<<<1, 32>>>(out);
    k_scatter<<<(2 * T_TOK) / 256, 256>>>();

    // join + GEMMs
    cudaStreamWaitEvent(0, eWg, 0);
    k_g1gate<<<dim3(HID / BN, NMPAD), 256, SMEM_DYN>>>();
    cudaStreamWaitEvent(0, eWu, 0);
    k_g1up<<<dim3(HID / BN, NMPAD), 256, SMEM_DYN>>>();
    cudaStreamWaitEvent(0, eWd, 0);
    cudaStreamWaitEvent(0, eZ, 0);
    k_gemm2_mma<<<dim3(DIM / BN, NMPAD), 256, SMEM_DYN>>>(out);
}

// round 13
// speedup vs baseline: 1.8334x; 1.1475x over previous
#include <cuda_runtime.h>
#include <cuda_fp16.h>
#include <cstdint>

#define T_TOK 8192
#define DIM   1024
#define HID   4096
#define NEXP  8
#define BM 128
#define BN 128
#define BK 64                      // k elements per stage (fp16)
#define NMPAD  136
#define MAXPAD (NMPAD * BM)

#define SAH 72                     // smem row stride in halves (144 bytes)
#define ATILEH (BM * SAH)          // 9216 halves per tile
#define STGB (2 * ATILEH * 2)      // 36864 bytes per stage (A+B)
#define NSTG 3
#define SMEM_DYN (NSTG * STGB)     // 110592 bytes -> 2 CTAs/SM

// ---------------- scratch ----------------
__device__ __half g_gh[(size_t)MAXPAD * HID];      // raw gate g in fp16
__device__ __half g_hh[(size_t)MAXPAD * HID];      // h = silu(g)*u in fp16
__device__ __half g_xh[(size_t)T_TOK * DIM];       // x in fp16
__device__ __half g_wgT[(size_t)NEXP * HID * DIM]; // w_gate^T [e][n][k] fp16
__device__ __half g_wuT[(size_t)NEXP * HID * DIM];
__device__ __half g_wdT[(size_t)NEXP * DIM * HID];
__device__ int    g_perm[MAXPAD];
__device__ float  g_permw[MAXPAD];
__device__ int    g_offpad[NEXP + 1];
__device__ int    g_cnt[NEXP];
__device__ int    g_cursor[NEXP];
__device__ float  g_probsum[NEXP];
__device__ int    g_topi[T_TOK * 2];
__device__ float  g_topw[T_TOK * 2];

// ---------------- helpers ----------------
__device__ __forceinline__ uint32_t smem_u32(const void* p) {
    uint32_t a;
    asm("{ .reg .u64 t; cvta.to.shared.u64 t, %1; cvt.u32.u64 %0, t; }"
        : "=r"(a) : "l"(p));
    return a;
}
__device__ __forceinline__ void cp16h(uint32_t d, const __half* s, uint32_t sz) {
    asm volatile("cp.async.cg.shared.global [%0], [%1], 16, %2;"
                 :: "r"(d), "l"(s), "r"(sz));
}
#define CP_COMMIT() asm volatile("cp.async.commit_group;" ::: "memory")
#define CP_WAIT1()  asm volatile("cp.async.wait_group 1;" ::: "memory")

__device__ __forceinline__ void mma_f16(float* c, const uint32_t* a,
                                        const uint32_t* b) {
    asm volatile(
        "mma.sync.aligned.m16n8k16.row.col.f32.f16.f16.f32 "
        "{%0,%1,%2,%3}, {%4,%5,%6,%7}, {%8,%9}, {%0,%1,%2,%3};"
        : "+f"(c[0]), "+f"(c[1]), "+f"(c[2]), "+f"(c[3])
        : "r"(a[0]), "r"(a[1]), "r"(a[2]), "r"(a[3]), "r"(b[0]), "r"(b[1]));
}

__device__ __forceinline__ void ldsm_x4(uint32_t* r, uint32_t addr) {
    asm volatile("ldmatrix.sync.aligned.m8n8.x4.shared.b16 {%0,%1,%2,%3}, [%4];"
                 : "=r"(r[0]), "=r"(r[1]), "=r"(r[2]), "=r"(r[3]) : "r"(addr));
}

// ---------------- small kernels ----------------
__global__ void k_init() {
    int i = blockIdx.x * blockDim.x + threadIdx.x;
    if (i < NEXP) { g_cnt[i] = 0; g_cursor[i] = 0; g_probsum[i] = 0.f; }
    if (i < MAXPAD) g_perm[i] = -1;
}

__global__ void k_zero_out(float4* out, int n4) {
    float4 z = make_float4(0.f, 0.f, 0.f, 0.f);
    for (int i = blockIdx.x * blockDim.x + threadIdx.x; i < n4;
         i += gridDim.x * blockDim.x)
        out[i] = z;
}

// transpose+convert: src fp32 [e][R][C] -> dst fp16 [e][C][R], 64x64 tiles
__global__ void k_tr(const float* __restrict__ src, int R, int C, int sel) {
    __half* dstb = (sel == 0) ? g_wgT : (sel == 1) ? g_wuT : g_wdT;
    __shared__ float t[64][65];
    size_t mo = (size_t)blockIdx.z * R * C;
    const float* s = src + mo;
    __half* d = dstb + mo;
    int c0 = blockIdx.x * 64, r0 = blockIdx.y * 64;
    int tx = threadIdx.x, ty = threadIdx.y;
#pragma unroll
    for (int j = ty; j < 64; j += 8) {
        float2 v = *(const float2*)&s[(size_t)(r0 + j) * C + c0 + tx * 2];
        t[j][tx * 2] = v.x; t[j][tx * 2 + 1] = v.y;
    }
    __syncthreads();
#pragma unroll
    for (int j = ty; j < 64; j += 8) {
        __half2 h = __floats2half2_rn(t[tx * 2][j], t[tx * 2 + 1][j]);
        *(__half2*)&d[(size_t)(c0 + j) * R + r0 + tx * 2] = h;
    }
}

// gating + fused x->fp16 conversion
__global__ void k_gate(const float* __restrict__ x, const float* __restrict__ gw) {
    int gwarp = (blockIdx.x * blockDim.x + threadIdx.x) >> 5;
    int lane  = threadIdx.x & 31;
    if (gwarp >= T_TOK) return;
    const float* xr = x + (size_t)gwarp * DIM;
    __half* xh = g_xh + (size_t)gwarp * DIM;

    float acc[NEXP];
#pragma unroll
    for (int e = 0; e < NEXP; e++) acc[e] = 0.f;
    for (int i = lane; i < DIM; i += 32) {
        float xv = xr[i];
        xh[i] = __float2half_rn(xv);
        float4 g0 = *(const float4*)(gw + (size_t)i * NEXP);
        float4 g1 = *(const float4*)(gw + (size_t)i * NEXP + 4);
        acc[0] += xv * g0.x; acc[1] += xv * g0.y;
        acc[2] += xv * g0.z; acc[3] += xv * g0.w;
        acc[4] += xv * g1.x; acc[5] += xv * g1.y;
        acc[6] += xv * g1.z; acc[7] += xv * g1.w;
    }
#pragma unroll
    for (int off = 16; off > 0; off >>= 1)
#pragma unroll
        for (int e = 0; e < NEXP; e++)
            acc[e] += __shfl_xor_sync(0xffffffffu, acc[e], off);

    float mx = acc[0];
#pragma unroll
    for (int e = 1; e < NEXP; e++) mx = fmaxf(mx, acc[e]);
    float p[NEXP], s = 0.f;
#pragma unroll
    for (int e = 0; e < NEXP; e++) { p[e] = __expf(acc[e] - mx); s += p[e]; }
    float inv = 1.f / s;
    if (lane < NEXP) atomicAdd(&g_probsum[lane], p[lane] * inv);

    if (lane == 0) {
        int i0 = 0;
#pragma unroll
        for (int e = 1; e < NEXP; e++) if (acc[e] > acc[i0]) i0 = e;
        int i1 = (i0 == 0) ? 1 : 0;
#pragma unroll
        for (int e = 0; e < NEXP; e++)
            if (e != i0 && acc[e] > acc[i1]) i1 = e;
        float m2 = fmaxf(acc[i0], acc[i1]);
        float e0 = __expf(acc[i0] - m2), e1 = __expf(acc[i1] - m2);
        float inv2 = 1.f / (e0 + e1);
        g_topi[2 * gwarp]     = i0; g_topw[2 * gwarp]     = e0 * inv2;
        g_topi[2 * gwarp + 1] = i1; g_topw[2 * gwarp + 1] = e1 * inv2;
        atomicAdd(&g_cnt[i0], 1);
        atomicAdd(&g_cnt[i1], 1);
    }
}

__global__ void k_offsets(float* __restrict__ out) {
    if (threadIdx.x != 0 || blockIdx.x != 0) return;
    int off = 0;
    for (int e = 0; e < NEXP; e++) {
        g_offpad[e] = off;
        off += ((g_cnt[e] + BM - 1) / BM) * BM;
    }
    g_offpad[NEXP] = off;
    float loss = 0.f;
    const float invT = 1.f / (float)T_TOK;
    for (int e = 0; e < NEXP; e++) {
        float m = g_probsum[e] * invT;
        out[(size_t)T_TOK * DIM + 1 + e] = m;
        loss += m * m;
    }
    out[(size_t)T_TOK * DIM] = (float)NEXP * loss;
}

__global__ void k_scatter() {
    int t = blockIdx.x * blockDim.x + threadIdx.x;
    if (t >= 2 * T_TOK) return;
    int e = g_topi[t];
    int pos = g_offpad[e] + atomicAdd(&g_cursor[e], 1);
    g_perm[pos]  = t >> 1;
    g_permw[pos] = g_topw[t];
}

// ---------------- GEMM1 core (gate or up), fp16 MMA, BK=64, 3-stage ------------
template<int UP>
__device__ __forceinline__ void gemm1_body(const __half* __restrict__ wT) {
    extern __shared__ __half smh[];
    int total = g_offpad[NEXP];
    int mbase = blockIdx.y * BM;
    if (mbase >= total) return;
    int e = 0;
#pragma unroll
    for (int i = 0; i < NEXP; i++) if (mbase >= g_offpad[i + 1]) e = i + 1;

    const __half* W = wT + (size_t)e * DIM * HID;   // [n=HID][k=DIM]
    int ncol = blockIdx.x * BN;

    int tid = threadIdx.x;
    uint32_t smb = smem_u32(smh);

    // loads: rows 32/pass, 8 chunks (16B) per 64-half row
    int row0 = tid >> 3, chk = (tid & 7) * 8;
    uint32_t adst[4], bdst[4];
    const __half *asrc[4], *bsrc[4];
    uint32_t asz[4];
#pragma unroll
    for (int p = 0; p < 4; p++) {
        int row = row0 + p * 32;
        adst[p] = (uint32_t)((row * SAH + chk) * 2);
        bdst[p] = (uint32_t)((ATILEH + row * SAH + chk) * 2);
        int tok = g_perm[mbase + row];
        asrc[p] = g_xh + ((tok >= 0) ? (size_t)tok * DIM : 0) + chk;
        asz[p]  = (tok >= 0) ? 16u : 0u;
        bsrc[p] = W + (size_t)(ncol + row) * DIM + chk;
    }

    int lane = tid & 31, gid = lane >> 2, tig = lane & 3;
    int wm = (tid >> 5) & 3, wn = tid >> 7;
    uint32_t aln = (uint32_t)(((wm * 32 + (lane & 15)) * SAH + (lane >> 4) * 8) * 2);
    uint32_t bln = (uint32_t)((ATILEH +
        (wn * 64 + (lane & 7) + ((lane >> 4) << 3)) * SAH +
        ((lane >> 3) & 1) * 8) * 2);

    float acc[2][8][4];
#pragma unroll
    for (int mt = 0; mt < 2; mt++)
#pragma unroll
        for (int nt = 0; nt < 8; nt++)
#pragma unroll
            for (int q = 0; q < 4; q++) acc[mt][nt][q] = 0.f;

    const int NT = DIM / BK;             // 16
#pragma unroll
    for (int t = 0; t < 2; t++) {        // prologue: 2 stages
        uint32_t base = smb + t * STGB;
        int k0 = t * BK;
#pragma unroll
        for (int p = 0; p < 4; p++) cp16h(base + adst[p], asrc[p] + k0, asz[p]);
#pragma unroll
        for (int p = 0; p < 4; p++) cp16h(base + bdst[p], bsrc[p] + k0, 16);
        CP_COMMIT();
    }

    for (int i = 0; i < NT; i++) {
        CP_WAIT1();
        __syncthreads();
        int t = i + 2;
        if (t < NT) {
            uint32_t base = smb + (t % NSTG) * STGB;
            int k0 = t * BK;
#pragma unroll
            for (int p = 0; p < 4; p++) cp16h(base + adst[p], asrc[p] + k0, asz[p]);
#pragma unroll
            for (int p = 0; p < 4; p++) cp16h(base + bdst[p], bsrc[p] + k0, 16);
        }
        CP_COMMIT();

        uint32_t stg = smb + (uint32_t)(i % NSTG) * STGB;
#pragma unroll
        for (int ks = 0; ks < 4; ks++) {     // four k16 steps per BK=64
            uint32_t a[2][4], b[4][4];
#pragma unroll
            for (int mt = 0; mt < 2; mt++)
                ldsm_x4(a[mt], stg + aln + (uint32_t)(mt * 16 * SAH * 2 + ks * 32));
#pragma unroll
            for (int j = 0; j < 4; j++)
                ldsm_x4(b[j], stg + bln + (uint32_t)(j * 16 * SAH * 2 + ks * 32));
#pragma unroll
            for (int mt = 0; mt < 2; mt++)
#pragma unroll
                for (int j = 0; j < 4; j++) {
                    mma_f16(acc[mt][2 * j],     a[mt], &b[j][0]);
                    mma_f16(acc[mt][2 * j + 1], a[mt], &b[j][2]);
                }
        }
    }

#pragma unroll
    for (int mt = 0; mt < 2; mt++) {
        int r = mbase + wm * 32 + mt * 16 + gid;
#pragma unroll
        for (int nt = 0; nt < 8; nt++) {
            int c = ncol + wn * 64 + nt * 8 + 2 * tig;
            if (UP) {
                float2 ga = __half22float2(*(__half2*)&g_gh[(size_t)r * HID + c]);
                float2 gb = __half22float2(*(__half2*)&g_gh[(size_t)(r + 8) * HID + c]);
                float h0 = ga.x * (1.f / (1.f + __expf(-ga.x))) * acc[mt][nt][0];
                float h1 = ga.y * (1.f / (1.f + __expf(-ga.y))) * acc[mt][nt][1];
                float h2 = gb.x * (1.f / (1.f + __expf(-gb.x))) * acc[mt][nt][2];
                float h3 = gb.y * (1.f / (1.f + __expf(-gb.y))) * acc[mt][nt][3];
                *(__half2*)&g_hh[(size_t)r * HID + c]       = __floats2half2_rn(h0, h1);
                *(__half2*)&g_hh[(size_t)(r + 8) * HID + c] = __floats2half2_rn(h2, h3);
            } else {
                *(__half2*)&g_gh[(size_t)r * HID + c] =
                    __floats2half2_rn(acc[mt][nt][0], acc[mt][nt][1]);
                *(__half2*)&g_gh[(size_t)(r + 8) * HID + c] =
                    __floats2half2_rn(acc[mt][nt][2], acc[mt][nt][3]);
            }
        }
    }
}

__global__ __launch_bounds__(256) void k_g1gate() { gemm1_body<0>(g_wgT); }
__global__ __launch_bounds__(256) void k_g1up()   { gemm1_body<1>(g_wuT); }

// ---------------- GEMM2: A = g_hh fp16, B = g_wdT fp16, atomic epilogue --------
__global__ __launch_bounds__(256) void k_gemm2_mma(float* __restrict__ out) {
    extern __shared__ __half smh[];
    int total = g_offpad[NEXP];
    int mbase = blockIdx.y * BM;
    if (mbase >= total) return;
    int e = 0;
#pragma unroll
    for (int i = 0; i < NEXP; i++) if (mbase >= g_offpad[i + 1]) e = i + 1;

    const __half* W = g_wdT + (size_t)e * DIM * HID;   // [n=DIM][k=HID]
    int ncol = blockIdx.x * BN;

    int tid = threadIdx.x;
    uint32_t smb = smem_u32(smh);

    int row0 = tid >> 3, chk = (tid & 7) * 8;
    uint32_t adst[4], bdst[4];
    const __half *asrc[4], *bsrc[4];
#pragma unroll
    for (int p = 0; p < 4; p++) {
        int row = row0 + p * 32;
        adst[p] = (uint32_t)((row * SAH + chk) * 2);
        bdst[p] = (uint32_t)((ATILEH + row * SAH + chk) * 2);
        asrc[p] = g_hh + (size_t)(mbase + row) * HID + chk;
        bsrc[p] = W + (size_t)(ncol + row) * HID + chk;
    }

    int lane = tid & 31, gid = lane >> 2, tig = lane & 3;
    int wm = (tid >> 5) & 3, wn = tid >> 7;
    uint32_t aln = (uint32_t)(((wm * 32 + (lane & 15)) * SAH + (lane >> 4) * 8) * 2);
    uint32_t bln = (uint32_t)((ATILEH +
        (wn * 64 + (lane & 7) + ((lane >> 4) << 3)) * SAH +
        ((lane >> 3) & 1) * 8) * 2);

    float acc[2][8][4];
#pragma unroll
    for (int mt = 0; mt < 2; mt++)
#pragma unroll
        for (int nt = 0; nt < 8; nt++)
#pragma unroll
            for (int q = 0; q < 4; q++) acc[mt][nt][q] = 0.f;

    const int NT = HID / BK;            // 64
#pragma unroll
    for (int t = 0; t < 2; t++) {
        uint32_t base = smb + t * STGB;
        int k0 = t * BK;
#pragma unroll
        for (int p = 0; p < 4; p++) cp16h(base + adst[p], asrc[p] + k0, 16);
#pragma unroll
        for (int p = 0; p < 4; p++) cp16h(base + bdst[p], bsrc[p] + k0, 16);
        CP_COMMIT();
    }

    for (int i = 0; i < NT; i++) {
        CP_WAIT1();
        __syncthreads();
        int t = i + 2;
        if (t < NT) {
            uint32_t base = smb + (t % NSTG) * STGB;
            int k0 = t * BK;
#pragma unroll
            for (int p = 0; p < 4; p++) cp16h(base + adst[p], asrc[p] + k0, 16);
#pragma unroll
            for (int p = 0; p < 4; p++) cp16h(base + bdst[p], bsrc[p] + k0, 16);
        }
        CP_COMMIT();

        uint32_t stg = smb + (uint32_t)(i % NSTG) * STGB;
#pragma unroll
        for (int ks = 0; ks < 4; ks++) {
            uint32_t a[2][4], b[4][4];
#pragma unroll
            for (int mt = 0; mt < 2; mt++)
                ldsm_x4(a[mt], stg + aln + (uint32_t)(mt * 16 * SAH * 2 + ks * 32));
#pragma unroll
            for (int j = 0; j < 4; j++)
                ldsm_x4(b[j], stg + bln + (uint32_t)(j * 16 * SAH * 2 + ks * 32));
#pragma unroll
            for (int mt = 0; mt < 2; mt++)
#pragma unroll
                for (int j = 0; j < 4; j++) {
                    mma_f16(acc[mt][2 * j],     a[mt], &b[j][0]);
                    mma_f16(acc[mt][2 * j + 1], a[mt], &b[j][2]);
                }
        }
    }

#pragma unroll
    for (int mt = 0; mt < 2; mt++) {
        int slot = mbase + wm * 32 + mt * 16 + gid;
        int tok0 = g_perm[slot],     tok1 = g_perm[slot + 8];
        float w0 = g_permw[slot],    w1 = g_permw[slot + 8];
#pragma unroll
        for (int nt = 0; nt < 8; nt++) {
            int c = ncol + wn * 64 + nt * 8 + 2 * tig;
            if (tok0 >= 0) {
                float* op = out + (size_t)tok0 * DIM + c;
                atomicAdd(op,     w0 * acc[mt][nt][0]);
                atomicAdd(op + 1, w0 * acc[mt][nt][1]);
            }
            if (tok1 >= 0) {
                float* op = out + (size_t)tok1 * DIM + c;
                atomicAdd(op,     w1 * acc[mt][nt][2]);
                atomicAdd(op + 1, w1 * acc[mt][nt][3]);
            }
        }
    }
}

// ---------------- launch: fork-join streams to overlap transposes ----------------
extern "C" void kernel_launch(void* const* d_in, const int* in_sizes, int n_in,
                              void* d_out, int out_size) {
    const float* x      = (const float*)d_in[0];
    const float* gate_w = (const float*)d_in[1];
    const float* w_gate = (const float*)d_in[2];
    const float* w_up   = (const float*)d_in[3];
    const float* w_down = (const float*)d_in[4];
    float* out = (float*)d_out;

    static bool inited = false;
    static cudaStream_t s1, s2;
    static cudaEvent_t eF, eWg, eWu, eWd, eZ;
    if (!inited) {
        cudaFuncSetAttribute(k_g1gate, cudaFuncAttributeMaxDynamicSharedMemorySize,
                             SMEM_DYN);
        cudaFuncSetAttribute(k_g1up, cudaFuncAttributeMaxDynamicSharedMemorySize,
                             SMEM_DYN);
        cudaFuncSetAttribute(k_gemm2_mma, cudaFuncAttributeMaxDynamicSharedMemorySize,
                             SMEM_DYN);
        cudaStreamCreateWithFlags(&s1, cudaStreamNonBlocking);
        cudaStreamCreateWithFlags(&s2, cudaStreamNonBlocking);
        cudaEventCreateWithFlags(&eF,  cudaEventDisableTiming);
        cudaEventCreateWithFlags(&eWg, cudaEventDisableTiming);
        cudaEventCreateWithFlags(&eWu, cudaEventDisableTiming);
        cudaEventCreateWithFlags(&eWd, cudaEventDisableTiming);
        cudaEventCreateWithFlags(&eZ,  cudaEventDisableTiming);
        inited = true;
    }

    // fork
    cudaEventRecord(eF, 0);
    cudaStreamWaitEvent(s1, eF, 0);
    cudaStreamWaitEvent(s2, eF, 0);

    // s1: weight transposes (independent of routing chain)
    dim3 trb(32, 8);
    k_tr<<<dim3(HID / 64, DIM / 64, NEXP), trb, 0, s1>>>(w_gate, DIM, HID, 0);
    cudaEventRecord(eWg, s1);
    k_tr<<<dim3(HID / 64, DIM / 64, NEXP), trb, 0, s1>>>(w_up,   DIM, HID, 1);
    cudaEventRecord(eWu, s1);
    k_tr<<<dim3(DIM / 64, HID / 64, NEXP), trb, 0, s1>>>(w_down, HID, DIM, 2);
    cudaEventRecord(eWd, s1);

    // s2: output zeroing (needed only by gemm2)
    k_zero_out<<<2048, 256, 0, s2>>>((float4*)out, (T_TOK * DIM) / 4);
    cudaEventRecord(eZ, s2);

    // main: routing chain
    k_init<<<MAXPAD / 256, 256>>>();
    k_gate<<<T_TOK / 8, 256>>>(x, gate_w);
    k_offsets<<<1, 32>>>(out);
    k_scatter<<<(2 * T_TOK) / 256, 256>>>();

    // join + GEMMs
    cudaStreamWaitEvent(0, eWg, 0);
    k_g1gate<<<dim3(HID / BN, NMPAD), 256, SMEM_DYN>>>();
    cudaStreamWaitEvent(0, eWu, 0);
    k_g1up<<<dim3(HID / BN, NMPAD), 256, SMEM_DYN>>>();
    cudaStreamWaitEvent(0, eWd, 0);
    cudaStreamWaitEvent(0, eZ, 0);
    k_gemm2_mma<<<dim3(DIM / BN, NMPAD), 256, SMEM_DYN>>>(out);
}